// round 7
// baseline (speedup 1.0000x reference)
#include <cuda_runtime.h>
#include <math.h>
#include <stdint.h>

#define NTOK 1024
#define DIMV 512
#define NHEAD 8
#define DHEAD 64
#define QBV 4
#define NPAIR 32
#define NROWS 4096
#define NALL 12288
#define NSEG 32768
#define INV8 ((float)(1.0 / (8.0 + 1e-6)))

__device__ float g_XLN[(size_t)NALL * DIMV];
__device__ float g_F[(size_t)NALL * DIMV];
__device__ float g_S[(size_t)NPAIR * NTOK * NTOK];
__device__ float g_OF[(size_t)NROWS * DIMV];
__device__ float g_rncq[NSEG], g_rnsq[NSEG], g_mq[NSEG], g_aq[NSEG];
__device__ float g_rnck[NSEG], g_rnsk[NSEG], g_tk[NSEG], g_sk[NSEG];
__device__ float g_kbar[NPAIR * DHEAD], g_T[NPAIR];
__device__ float g_kpart[NPAIR * 8 * 64];
__device__ float g_qgpart[2 * 8 * 8 * 64];
__device__ float g_qg[NHEAD * DHEAD], g_kg[NHEAD * DHEAD];
__device__ float g_rpart[(size_t)NSEG * 16 * 3];
__device__ double g_mpart[(size_t)NPAIR * 64 * 5];
__device__ double g_mom[NHEAD * 9];
__device__ float g_coef[16];

// ---------------- helpers ---------------------------------------------------
__device__ __forceinline__ uint32_t f2tf32(float x) {
    uint32_t r;
    asm("cvt.rna.tf32.f32 %0, %1;" : "=r"(r) : "f"(x));
    return r;
}
__device__ __forceinline__ void mma_tf32(float* c, const uint32_t* a, uint32_t b0, uint32_t b1) {
    asm volatile(
        "mma.sync.aligned.m16n8k8.row.col.f32.tf32.tf32.f32 "
        "{%0,%1,%2,%3}, {%4,%5,%6,%7}, {%8,%9}, {%0,%1,%2,%3};"
        : "+f"(c[0]), "+f"(c[1]), "+f"(c[2]), "+f"(c[3])
        : "r"(a[0]), "r"(a[1]), "r"(a[2]), "r"(a[3]), "r"(b0), "r"(b1));
}

// ---------------- LayerNorm of q,k,v stacked --------------------------------
__global__ void k_ln(const float* __restrict__ q, const float* __restrict__ k,
                     const float* __restrict__ v, const float* __restrict__ g,
                     const float* __restrict__ b) {
    int r = blockIdx.x;
    const float* src = (r < NROWS) ? q + (size_t)r * DIMV
                     : (r < 2 * NROWS) ? k + (size_t)(r - NROWS) * DIMV
                     : v + (size_t)(r - 2 * NROWS) * DIMV;
    int tid = threadIdx.x;  // 128
    float x[4]; float s = 0.f, s2 = 0.f;
#pragma unroll
    for (int j = 0; j < 4; j++) { x[j] = src[tid + j * 128]; s += x[j]; s2 += x[j] * x[j]; }
    __shared__ float shs[4], shs2[4];
    for (int off = 16; off >= 1; off >>= 1) {
        s += __shfl_down_sync(0xffffffffu, s, off);
        s2 += __shfl_down_sync(0xffffffffu, s2, off);
    }
    int lane = tid & 31, w = tid >> 5;
    if (lane == 0) { shs[w] = s; shs2[w] = s2; }
    __syncthreads();
    __shared__ float s_mu, s_rstd;
    if (tid == 0) {
        float S = shs[0] + shs[1] + shs[2] + shs[3];
        float S2 = shs2[0] + shs2[1] + shs2[2] + shs2[3];
        float mu = S / DIMV;
        s_mu = mu; s_rstd = rsqrtf(S2 / DIMV - mu * mu + 1e-5f);
    }
    __syncthreads();
    float mu = s_mu, rstd = s_rstd;
#pragma unroll
    for (int j = 0; j < 4; j++) {
        int c = tid + j * 128;
        g_XLN[(size_t)r * DIMV + c] = (x[j] - mu) * rstd * g[c] + b[c];
    }
}

// ---------------- tf32x3 MMA GEMM: C = A[M,K] @ B[K,N] (+bias) --------------
__global__ __launch_bounds__(256) void k_mma(
        const float* __restrict__ A, const float* __restrict__ B,
        const float* __restrict__ bias, float* __restrict__ C,
        int M, int N, int K) {
    __shared__ float Ah[16][136], Al[16][136], Bh[16][136], Bl[16][136];
    int tid = threadIdx.x;
    int lane = tid & 31, wid = tid >> 5;
    int g = lane >> 2, tg = lane & 3;
    int wm = (wid & 3) * 32, wn = (wid >> 2) * 64;
    int m0 = blockIdx.y * 128, n0 = blockIdx.x * 128;
    int arow = tid & 127, akg = tid >> 7;
    int bng = tid & 31, bk0 = tid >> 5;
    const float* Arow = A + (size_t)(m0 + arow) * K;
    float4 va[2], vb[2];
#pragma unroll
    for (int it = 0; it < 2; it++) {
        va[it] = *(const float4*)&Arow[(akg + 2 * it) * 4];
        vb[it] = *(const float4*)&B[(size_t)(bk0 + 8 * it) * N + n0 + bng * 4];
    }
    float acc[2][8][4];
#pragma unroll
    for (int a = 0; a < 2; a++)
#pragma unroll
        for (int b = 0; b < 8; b++)
#pragma unroll
            for (int c = 0; c < 4; c++) acc[a][b][c] = 0.f;
    for (int kc = 0; kc < K; kc += 16) {
        __syncthreads();
#pragma unroll
        for (int it = 0; it < 2; it++) {
            int kka = (akg + 2 * it) * 4;
            float xs[4] = {va[it].x, va[it].y, va[it].z, va[it].w};
#pragma unroll
            for (int c = 0; c < 4; c++) {
                float hf = __uint_as_float(f2tf32(xs[c]));
                Ah[kka + c][arow] = hf;
                Al[kka + c][arow] = __uint_as_float(f2tf32(xs[c] - hf));
            }
            int kkb = bk0 + 8 * it;
            float ys[4] = {vb[it].x, vb[it].y, vb[it].z, vb[it].w};
            float hb[4], lb[4];
#pragma unroll
            for (int c = 0; c < 4; c++) {
                hb[c] = __uint_as_float(f2tf32(ys[c]));
                lb[c] = __uint_as_float(f2tf32(ys[c] - hb[c]));
            }
            *(float4*)&Bh[kkb][bng * 4] = make_float4(hb[0], hb[1], hb[2], hb[3]);
            *(float4*)&Bl[kkb][bng * 4] = make_float4(lb[0], lb[1], lb[2], lb[3]);
        }
        __syncthreads();
        if (kc + 16 < K) {
            int k0 = kc + 16;
#pragma unroll
            for (int it = 0; it < 2; it++) {
                va[it] = *(const float4*)&Arow[k0 + (akg + 2 * it) * 4];
                vb[it] = *(const float4*)&B[(size_t)(k0 + bk0 + 8 * it) * N + n0 + bng * 4];
            }
        }
#pragma unroll
        for (int ks = 0; ks < 16; ks += 8) {
            uint32_t ah[2][4], al_[2][4];
#pragma unroll
            for (int mt = 0; mt < 2; mt++) {
                int mb = wm + mt * 16 + g;
                ah[mt][0] = __float_as_uint(Ah[ks + tg][mb]);
                ah[mt][1] = __float_as_uint(Ah[ks + tg][mb + 8]);
                ah[mt][2] = __float_as_uint(Ah[ks + tg + 4][mb]);
                ah[mt][3] = __float_as_uint(Ah[ks + tg + 4][mb + 8]);
                al_[mt][0] = __float_as_uint(Al[ks + tg][mb]);
                al_[mt][1] = __float_as_uint(Al[ks + tg][mb + 8]);
                al_[mt][2] = __float_as_uint(Al[ks + tg + 4][mb]);
                al_[mt][3] = __float_as_uint(Al[ks + tg + 4][mb + 8]);
            }
#pragma unroll
            for (int nt = 0; nt < 8; nt++) {
                int nb = wn + nt * 8 + g;
                uint32_t bh0 = __float_as_uint(Bh[ks + tg][nb]);
                uint32_t bh1 = __float_as_uint(Bh[ks + tg + 4][nb]);
                uint32_t bl0 = __float_as_uint(Bl[ks + tg][nb]);
                uint32_t bl1 = __float_as_uint(Bl[ks + tg + 4][nb]);
#pragma unroll
                for (int mt = 0; mt < 2; mt++) {
                    mma_tf32(acc[mt][nt], ah[mt], bh0, bh1);
                    mma_tf32(acc[mt][nt], ah[mt], bl0, bl1);
                    mma_tf32(acc[mt][nt], al_[mt], bh0, bh1);
                }
            }
        }
    }
#pragma unroll
    for (int mt = 0; mt < 2; mt++) {
        int row0 = m0 + wm + mt * 16 + g;
#pragma unroll
        for (int nt = 0; nt < 8; nt++) {
            int col = n0 + wn + nt * 8 + 2 * tg;
            float bx = bias ? bias[col] : 0.f;
            float by = bias ? bias[col + 1] : 0.f;
            *(float2*)&C[(size_t)row0 * N + col] =
                make_float2(acc[mt][nt][0] + bx, acc[mt][nt][1] + by);
            *(float2*)&C[(size_t)(row0 + 8) * N + col] =
                make_float2(acc[mt][nt][2] + bx, acc[mt][nt][3] + by);
        }
    }
}

// ---------------- per (row, head) stats for fq / fk -------------------------
__global__ void k_rowstats() {
    int tid = threadIdx.x;
    int w = tid >> 5, lane = tid & 31;
    int gw = blockIdx.x * 8 + w;
    int tensor = gw >> 15;
    int rem = gw & 32767;
    int row = rem >> 3, h = rem & 7;
    const float* base = &g_F[(size_t)(tensor * NROWS + row) * DIMV + h * DHEAD];
    float v1 = base[lane], v2 = base[lane + 32];
    float s = v1 + v2, sq = v1 * v1 + v2 * v2;
    for (int off = 16; off >= 1; off >>= 1) {
        s += __shfl_down_sync(0xffffffffu, s, off);
        sq += __shfl_down_sync(0xffffffffu, sq, off);
    }
    if (lane == 0) {
        int sidx = h * NROWS + row;
        float nrm = sqrtf(sq);
        if (tensor == 0) {
            g_rncq[sidx] = 1.f / (nrm + 1e-8f);
            g_rnsq[sidx] = 1.f / fmaxf(nrm, 1e-6f);
            g_mq[sidx] = s * (1.f / DHEAD);
        } else {
            g_rnck[sidx] = 1.f / (nrm + 1e-8f);
            g_rnsk[sidx] = 1.f / fmaxf(nrm, 1e-6f);
            g_tk[sidx] = s;
        }
    }
}

// ---------------- kbar two-stage --------------------------------------------
__global__ void k_kbar1() {
    int p = blockIdx.x, seg = blockIdx.y;
    int h = p >> 2, qb = p & 3;
    int tid = threadIdx.x, d = tid & 63, rr = tid >> 6;
    float acc = 0.f;
    int base = qb * NTOK + seg * 128;
    for (int m = rr; m < 128; m += 4)
        acc += g_F[(size_t)(NROWS + base + m) * DIMV + h * DHEAD + d];
    __shared__ float red[256];
    red[tid] = acc;
    __syncthreads();
    if (rr == 0) g_kpart[(p * 8 + seg) * 64 + d] = red[d] + red[64 + d] + red[128 + d] + red[192 + d];
}
__global__ void k_kbar2() {
    int p = blockIdx.x, d = threadIdx.x;
    float s = 0.f;
    for (int seg = 0; seg < 8; seg++) s += g_kpart[(p * 8 + seg) * 64 + d];
    float kb = s * (1.f / NTOK);
    g_kbar[p * DHEAD + d] = kb;
    __shared__ float sh[64];
    sh[d] = kb;
    __syncthreads();
    if (d == 0) {
        float t = 0.f;
        for (int i = 0; i < 64; i++) t += sh[i];
        g_T[p] = t;
    }
}

// ---------------- a[n] = fq . kbar ; sk[m] = tk[m] - T ----------------------
__global__ void k_ask() {
    int tid = threadIdx.x, w = tid >> 5, lane = tid & 31;
    int t = blockIdx.x * 8 + w;
    int p = t >> 10, n = t & 1023;
    int h = p >> 2, qb = p & 3;
    const float* fq = &g_F[(size_t)(qb * NTOK + n) * DIMV + h * DHEAD];
    const float* kb = &g_kbar[p * DHEAD];
    float s = fq[lane] * kb[lane] + fq[lane + 32] * kb[lane + 32];
    for (int off = 16; off >= 1; off >>= 1) s += __shfl_down_sync(0xffffffffu, s, off);
    if (lane == 0) { g_aq[t] = s; g_sk[t] = g_tk[t] - g_T[p]; }
}

// ---------------- qg/kg two-stage -------------------------------------------
__global__ void k_qgkg1() {
    int h = blockIdx.x, tensor = blockIdx.y, seg = blockIdx.z;
    int tid = threadIdx.x, d = tid & 63, rr = tid >> 6;
    float acc = 0.f;
    for (int r = rr; r < 512; r += 4)
        acc += g_F[(size_t)(tensor * NROWS + seg * 512 + r) * DIMV + h * DHEAD + d];
    __shared__ float red[256];
    red[tid] = acc;
    __syncthreads();
    if (rr == 0)
        g_qgpart[((tensor * 8 + h) * 8 + seg) * 64 + d] = red[d] + red[64 + d] + red[128 + d] + red[192 + d];
}
__global__ void k_qgkg2() {
    int h = blockIdx.x, tensor = blockIdx.y, d = threadIdx.x;
    float s = 0.f;
    for (int seg = 0; seg < 8; seg++) s += g_qgpart[((tensor * 8 + h) * 8 + seg) * 64 + d];
    (tensor == 0 ? g_qg : g_kg)[h * 64 + d] = s * (1.f / NROWS);
}

// ---------------- S = fq @ fk^T via tf32x3 MMA + moment partials ------------
__global__ __launch_bounds__(256) void k_sstats() {
    int p = blockIdx.z, h = p >> 2, qb = p & 3;
    int n0 = blockIdx.y * 128, m0 = blockIdx.x * 128;
    __shared__ float Ah[16][136], Al[16][136], Bh[16][136], Bl[16][136];
    __shared__ float rowv[4][128];
    __shared__ float colv[3][128];
    __shared__ float wsum[8];
    int tid = threadIdx.x;
    int lane = tid & 31, wid = tid >> 5;
    int g = lane >> 2, tg = lane & 3;
    int wm = (wid & 3) * 32, wnb = wid >> 2;
    int wn = wnb * 64;
    int lrow = tid & 127, lhalf = tid >> 7;
    const float* qsrc = &g_F[(size_t)(qb * NTOK + n0 + lrow) * DIMV + h * DHEAD];
    const float* ksrc = &g_F[(size_t)(NROWS + qb * NTOK + m0 + lrow) * DIMV + h * DHEAD];
    if (tid < 128) {
        int sr = p * NTOK + n0 + tid;
        rowv[0][tid] = g_rncq[sr]; rowv[1][tid] = g_rnsq[sr];
        rowv[2][tid] = g_aq[sr];   rowv[3][tid] = g_mq[sr];
        int sc = p * NTOK + m0 + tid;
        colv[0][tid] = g_rnck[sc]; colv[1][tid] = g_rnsk[sc]; colv[2][tid] = g_sk[sc];
    }
    float acc[2][8][4];
#pragma unroll
    for (int a = 0; a < 2; a++)
#pragma unroll
        for (int b = 0; b < 8; b++)
#pragma unroll
            for (int c = 0; c < 4; c++) acc[a][b][c] = 0.f;
    for (int kc = 0; kc < 64; kc += 16) {
        float4 va0 = *(const float4*)&qsrc[kc + 8 * lhalf];
        float4 va1 = *(const float4*)&qsrc[kc + 8 * lhalf + 4];
        float4 vb0 = *(const float4*)&ksrc[kc + 8 * lhalf];
        float4 vb1 = *(const float4*)&ksrc[kc + 8 * lhalf + 4];
        __syncthreads();
        float xa[8] = {va0.x, va0.y, va0.z, va0.w, va1.x, va1.y, va1.z, va1.w};
        float xb[8] = {vb0.x, vb0.y, vb0.z, vb0.w, vb1.x, vb1.y, vb1.z, vb1.w};
#pragma unroll
        for (int c = 0; c < 8; c++) {
            int kl = 8 * lhalf + c;
            float hf = __uint_as_float(f2tf32(xa[c]));
            Ah[kl][lrow] = hf;
            Al[kl][lrow] = __uint_as_float(f2tf32(xa[c] - hf));
            float hg = __uint_as_float(f2tf32(xb[c]));
            Bh[kl][lrow] = hg;
            Bl[kl][lrow] = __uint_as_float(f2tf32(xb[c] - hg));
        }
        __syncthreads();
#pragma unroll
        for (int ks = 0; ks < 16; ks += 8) {
            uint32_t ah[2][4], al_[2][4];
#pragma unroll
            for (int mt = 0; mt < 2; mt++) {
                int mb = wm + mt * 16 + g;
                ah[mt][0] = __float_as_uint(Ah[ks + tg][mb]);
                ah[mt][1] = __float_as_uint(Ah[ks + tg][mb + 8]);
                ah[mt][2] = __float_as_uint(Ah[ks + tg + 4][mb]);
                ah[mt][3] = __float_as_uint(Ah[ks + tg + 4][mb + 8]);
                al_[mt][0] = __float_as_uint(Al[ks + tg][mb]);
                al_[mt][1] = __float_as_uint(Al[ks + tg][mb + 8]);
                al_[mt][2] = __float_as_uint(Al[ks + tg + 4][mb]);
                al_[mt][3] = __float_as_uint(Al[ks + tg + 4][mb + 8]);
            }
#pragma unroll
            for (int nt = 0; nt < 8; nt++) {
                int nb = wn + nt * 8 + g;
                uint32_t bh0 = __float_as_uint(Bh[ks + tg][nb]);
                uint32_t bh1 = __float_as_uint(Bh[ks + tg + 4][nb]);
                uint32_t bl0 = __float_as_uint(Bl[ks + tg][nb]);
                uint32_t bl1 = __float_as_uint(Bl[ks + tg + 4][nb]);
#pragma unroll
                for (int mt = 0; mt < 2; mt++) {
                    mma_tf32(acc[mt][nt], ah[mt], bh0, bh1);
                    mma_tf32(acc[mt][nt], ah[mt], bl0, bl1);
                    mma_tf32(acc[mt][nt], al_[mt], bh0, bh1);
                }
            }
        }
    }
    // epilogue
    float tc = 0.f, tc2 = 0.f, tp = 0.f, tp2 = 0.f, tcp = 0.f;
    float rcos[4] = {}, rpre[4] = {}, rmar[4] = {};
    size_t sbase = ((size_t)p << 20);
#pragma unroll
    for (int mt = 0; mt < 2; mt++) {
#pragma unroll
        for (int half = 0; half < 2; half++) {
            int row = wm + mt * 16 + half * 8 + g;
            int ri = mt * 2 + half;
            float rq = rowv[0][row], rsq = rowv[1][row];
            float aqv = rowv[2][row], mqv = rowv[3][row];
#pragma unroll
            for (int nt = 0; nt < 8; nt++) {
                int col0 = wn + nt * 8 + 2 * tg;
                float s0 = acc[mt][nt][half * 2 + 0];
                float s1 = acc[mt][nt][half * 2 + 1];
                float cos0 = fminf(fmaxf(s0 * rq * colv[0][col0], -0.99f), 0.99f);
                float cos1 = fminf(fmaxf(s1 * rq * colv[0][col0 + 1], -0.99f), 0.99f);
                float cs0 = fminf(fmaxf(s0 * rsq * colv[1][col0], -0.99f), 0.99f);
                float cs1 = fminf(fmaxf(s1 * rsq * colv[1][col0 + 1], -0.99f), 0.99f);
                float ma0 = fminf(fmaxf(0.01f - cs0, 0.f), 10.f);
                float ma1 = fminf(fmaxf(0.01f - cs1, 0.f), 10.f);
                float pr0 = (s0 - aqv - mqv * colv[2][col0]) * INV8;
                float pr1 = (s1 - aqv - mqv * colv[2][col0 + 1]) * INV8;
                tc += cos0 + cos1; tc2 += cos0 * cos0 + cos1 * cos1;
                tp += pr0 + pr1;   tp2 += pr0 * pr0 + pr1 * pr1;
                tcp += cos0 * pr0 + cos1 * pr1;
                rcos[ri] += cos0 + cos1; rpre[ri] += pr0 + pr1; rmar[ri] += ma0 + ma1;
                *(float2*)&g_S[sbase + (size_t)(n0 + row) * NTOK + m0 + col0] =
                    make_float2(s0, s1);
            }
        }
    }
    // per-row partials: reduce over the 4-lane quad (same g, tg=0..3)
#pragma unroll
    for (int ri = 0; ri < 4; ri++) {
        float vc = rcos[ri], vp = rpre[ri], vm = rmar[ri];
        vc += __shfl_xor_sync(0xffffffffu, vc, 1, 4);
        vc += __shfl_xor_sync(0xffffffffu, vc, 2, 4);
        vp += __shfl_xor_sync(0xffffffffu, vp, 1, 4);
        vp += __shfl_xor_sync(0xffffffffu, vp, 2, 4);
        vm += __shfl_xor_sync(0xffffffffu, vm, 1, 4);
        vm += __shfl_xor_sync(0xffffffffu, vm, 2, 4);
        if (tg == 0) {
            int row = wm + (ri >> 1) * 16 + (ri & 1) * 8 + g;
            size_t s = ((size_t)(p * NTOK + n0 + row) * 16 + blockIdx.x * 2 + wnb) * 3;
            g_rpart[s + 0] = vc; g_rpart[s + 1] = vp; g_rpart[s + 2] = vm;
        }
    }
    // 5 moments block reduce
    float vals[5] = {tc, tc2, tp, tp2, tcp};
    for (int v = 0; v < 5; v++) {
        float x = vals[v];
        for (int off = 16; off >= 1; off >>= 1) x += __shfl_down_sync(0xffffffffu, x, off);
        if (lane == 0) wsum[wid] = x;
        __syncthreads();
        if (tid == 0) {
            float s = 0.f;
            for (int i = 0; i < 8; i++) s += wsum[i];
            g_mpart[(size_t)(p * 64 + blockIdx.y * 8 + blockIdx.x) * 5 + v] = (double)s;
        }
        __syncthreads();
    }
}

// ---------------- per-head reductions: rows + moments -----------------------
__global__ void k_rowfinish() {
    int h = blockIdx.x, tid = threadIdx.x;
    double a5 = 0, a6 = 0, a7 = 0, a8 = 0;
    for (int r = tid; r < NROWS; r += 256) {
        int s = h * NROWS + r;
        float rc = 0.f, rp = 0.f, rm = 0.f;
        for (int mb = 0; mb < 16; mb++) {
            size_t idx = ((size_t)s * 16 + mb) * 3;
            rc += g_rpart[idx]; rp += g_rpart[idx + 1]; rm += g_rpart[idx + 2];
        }
        double v = (double)rm * (1.0 / 1024.0);
        a5 += 1024.0 * v; a6 += 1024.0 * v * v;
        a7 += v * (double)rc; a8 += v * (double)rp;
    }
    __shared__ double sh[256];
    double vals[4] = {a5, a6, a7, a8};
    for (int v = 0; v < 4; v++) {
        sh[tid] = vals[v];
        __syncthreads();
        for (int s = 128; s >= 1; s >>= 1) {
            if (tid < s) sh[tid] += sh[tid + s];
            __syncthreads();
        }
        if (tid == 0) g_mom[h * 9 + 5 + v] = sh[0];
        __syncthreads();
    }
    for (int v = 0; v < 5; v++) {
        int qb = tid >> 6, blk = tid & 63;
        sh[tid] = g_mpart[(size_t)((h * 4 + qb) * 64 + blk) * 5 + v];
        __syncthreads();
        for (int s = 128; s >= 1; s >>= 1) {
            if (tid < s) sh[tid] += sh[tid + s];
            __syncthreads();
        }
        if (tid == 0) g_mom[h * 9 + v] = sh[0];
        __syncthreads();
    }
}

__device__ double dev_std(double s, double s2, double N) {
    double v = (s2 - s * s / N) / (N - 1.0);
    return v > 0.0 ? sqrt(v) : 0.0;
}

// ---------------- finalize: MLP weights + global scalars --------------------
__global__ void k_finalize(const float* __restrict__ W1, const float* __restrict__ b1,
                           const float* __restrict__ lng, const float* __restrict__ lnb,
                           const float* __restrict__ W2, const float* __restrict__ b2,
                           const float* __restrict__ W3, const float* __restrict__ b3,
                           const float* __restrict__ wtp) {
    __shared__ float ws[8][3];
    int tid = threadIdx.x;
    if (tid < 8) {
        int h = tid;
        float y[64];
        for (int i = 0; i < 64; i++) {
            float a = b1[i];
            for (int j = 0; j < 64; j++) a += g_qg[h * 64 + j] * W1[j * 64 + i];
            for (int j = 0; j < 64; j++) a += g_kg[h * 64 + j] * W1[(64 + j) * 64 + i];
            y[i] = a;
        }
        float mu = 0.f;
        for (int i = 0; i < 64; i++) mu += y[i];
        mu *= (1.f / 64.f);
        float var = 0.f;
        for (int i = 0; i < 64; i++) { float d = y[i] - mu; var += d * d; }
        float rstd = rsqrtf(var * (1.f / 64.f) + 1e-5f);
        for (int i = 0; i < 64; i++)
            y[i] = fmaxf((y[i] - mu) * rstd * lng[i] + lnb[i], 0.f);
        float hh[32];
        for (int o = 0; o < 32; o++) {
            float a = b2[o];
            for (int i = 0; i < 64; i++) a += y[i] * W2[i * 32 + o];
            hh[o] = fmaxf(a, 0.f);
        }
        float l[3];
        for (int c = 0; c < 3; c++) {
            float a = b3[c];
            for (int o = 0; o < 32; o++) a += hh[o] * W3[o * 3 + c];
            l[c] = a;
        }
        float mx = fmaxf(l[0], fmaxf(l[1], l[2]));
        float e0 = expf(l[0] - mx), e1 = expf(l[1] - mx), e2 = expf(l[2] - mx);
        float sm = e0 + e1 + e2;
        l[0] = e0 / sm; l[1] = e1 / sm; l[2] = e2 / sm;
        float wt = fminf(fmaxf(wtp[0], 0.1f), 20.f);
        l[0] /= wt; l[1] /= wt; l[2] /= wt;
        mx = fmaxf(l[0], fmaxf(l[1], l[2]));
        e0 = expf(l[0] - mx); e1 = expf(l[1] - mx); e2 = expf(l[2] - mx);
        sm = e0 + e1 + e2;
        l[0] = e0 / sm; l[1] = e1 / sm; l[2] = e2 / sm;
        for (int c = 0; c < 3; c++) l[c] = fminf(fmaxf(l[c], 0.05f), 0.8f);
        sm = l[0] + l[1] + l[2];
        ws[h][0] = l[0] / sm; ws[h][1] = l[1] / sm; ws[h][2] = l[2] / sm;
    }
    __syncthreads();
    if (tid == 0) {
        const double N = 33554432.0;
        double Sc = 0, Sc2 = 0, Sp = 0, Sp2 = 0, Sv = 0, Sv2 = 0;
        for (int h = 0; h < 8; h++) {
            Sc += g_mom[h * 9 + 0]; Sc2 += g_mom[h * 9 + 1];
            Sp += g_mom[h * 9 + 2]; Sp2 += g_mom[h * 9 + 3];
            Sv += g_mom[h * 9 + 5]; Sv2 += g_mom[h * 9 + 6];
        }
        double cstd = dev_std(Sc, Sc2, N);
        double pstd = dev_std(Sp, Sp2, N);
        double vstd = dev_std(Sv, Sv2, N);
        double base = 0.001 / 1024.0;
        double reg = (pstd < 1e-6) ? base * 10.0 : base;
        double cn = cstd + 1e-6;
        double covn = reg * pstd + 1e-6;
        double vn = vstd + 1e-6;
        double cscale = (cn < 1e-4) ? 0.1 : 1.0;
        double Sd = 0, Sd2 = 0, al[8], be[8];
        for (int h = 0; h < 8; h++) {
            double a = (double)ws[h][0] * cscale / cn;
            double bb = (double)ws[h][1] * 0.5 / covn;
            double gg = (double)ws[h][2] * 0.5 / vn;
            al[h] = a; be[h] = bb;
            double m0 = g_mom[h * 9 + 0], m1 = g_mom[h * 9 + 1];
            double m2 = g_mom[h * 9 + 2], m3 = g_mom[h * 9 + 3];
            double m4 = g_mom[h * 9 + 4], m5 = g_mom[h * 9 + 5];
            double m6 = g_mom[h * 9 + 6], m7 = g_mom[h * 9 + 7];
            double m8 = g_mom[h * 9 + 8];
            Sd += a * m0 + bb * reg * m2 + gg * m5;
            Sd2 += a * a * m1 + bb * bb * reg * reg * m3 + gg * gg * m6
                 + 2.0 * a * bb * reg * m4 + 2.0 * a * gg * m7 + 2.0 * bb * gg * reg * m8;
        }
        double dvar = (Sd2 - Sd * Sd / N) / (N - 1.0);
        double dstd = dvar > 0.0 ? sqrt(dvar) : 0.0;
        double temp = (dstd < 1e-6) ? 0.1 : 0.3 + dstd;
        temp = fmin(fmax(temp, 0.1), 5.0);
        for (int h = 0; h < 8; h++) {
            g_coef[h] = (float)(al[h] / temp);
            g_coef[8 + h] = (float)(be[h] * reg / temp);
        }
    }
}

// ---------------- online softmax + AV (128-row blocks, dyn smem) ------------
#define VS_PITCH 68
#define PS_PITCH 69
#define SMAV_FLOATS (64 * VS_PITCH + 128 * PS_PITCH + 128 * 3 + 64 * 2)
__global__ __launch_bounds__(256) void k_softmaxAV() {
    extern __shared__ float smp[];
    float (*Vs)[VS_PITCH] = (float(*)[VS_PITCH])smp;
    float (*Ps)[PS_PITCH] = (float(*)[PS_PITCH])(smp + 64 * VS_PITCH);
    float* rq = smp + 64 * VS_PITCH + 128 * PS_PITCH;
    float* aqv = rq + 128;
    float* mqv = aqv + 128;
    float* rk = mqv + 128;
    float* skv = rk + 64;
    int p = blockIdx.y, h = p >> 2, qb = p & 3;
    int n0 = blockIdx.x * 128;
    int tid = threadIdx.x;
    int tx = tid & 15, ty = tid >> 4;
    float cA = g_coef[h], cB = g_coef[8 + h];
    if (tid < 128) {
        int s = p * NTOK + n0 + tid;
        rq[tid] = g_rncq[s]; aqv[tid] = g_aq[s]; mqv[tid] = g_mq[s];
    }
    float acc[8][4] = {};
    float rmax[8], den[8] = {};
#pragma unroll
    for (int i = 0; i < 8; i++) rmax[i] = -1e30f;
    size_t sbase = ((size_t)p << 20);
    for (int mt = 0; mt < 16; mt++) {
        int m0 = mt * 64;
        __syncthreads();
#pragma unroll
        for (int it = 0; it < 4; it++) {
            int lin = tid + it * 256;
            int r = lin >> 4, ks = (lin & 15) * 4;
            float4 v4 = *(const float4*)&g_F[(size_t)(2 * NROWS + qb * NTOK + m0 + r) * DIMV + h * DHEAD + ks];
            Vs[r][ks + 0] = v4.x; Vs[r][ks + 1] = v4.y; Vs[r][ks + 2] = v4.z; Vs[r][ks + 3] = v4.w;
        }
        if (tid < 64) {
            int s = p * NTOK + m0 + tid;
            rk[tid] = g_rnck[s]; skv[tid] = g_sk[s];
        }
        __syncthreads();
#pragma unroll
        for (int i = 0; i < 8; i++) {
            int row = 8 * ty + i;
            float4 s4 = *(const float4*)&g_S[sbase + (size_t)(n0 + row) * NTOK + m0 + 4 * tx];
            float rr = rq[row], av = aqv[row], mv = mqv[row];
            float z[4];
#pragma unroll
            for (int j = 0; j < 4; j++) {
                int col = 4 * tx + j;
                float sv = (&s4.x)[j];
                float cosv = fminf(fmaxf(sv * rr * rk[col], -0.99f), 0.99f);
                float pre = (sv - av - mv * skv[col]) * INV8;
                z[j] = cA * cosv + cB * pre;
            }
            float tm = fmaxf(fmaxf(z[0], z[1]), fmaxf(z[2], z[3]));
            for (int off = 8; off >= 1; off >>= 1)
                tm = fmaxf(tm, __shfl_xor_sync(0xffffffffu, tm, off, 16));
            float nm = fmaxf(rmax[i], tm);
            float corr = __expf(rmax[i] - nm);
            float ps = 0.f;
#pragma unroll
            for (int j = 0; j < 4; j++) {
                float pv = __expf(z[j] - nm);
                Ps[row][4 * tx + j] = pv;
                ps += pv;
            }
            for (int off = 8; off >= 1; off >>= 1)
                ps += __shfl_xor_sync(0xffffffffu, ps, off, 16);
            den[i] = den[i] * corr + ps;
            rmax[i] = nm;
#pragma unroll
            for (int j = 0; j < 4; j++) acc[i][j] *= corr;
        }
        __syncthreads();
#pragma unroll 4
        for (int m = 0; m < 64; m++) {
            float4 v4 = *(float4*)&Vs[m][4 * tx];
#pragma unroll
            for (int i = 0; i < 8; i++) {
                float pv = Ps[8 * ty + i][m];
                acc[i][0] += pv * v4.x; acc[i][1] += pv * v4.y;
                acc[i][2] += pv * v4.z; acc[i][3] += pv * v4.w;
            }
        }
    }
#pragma unroll
    for (int i = 0; i < 8; i++) {
        float inv = 1.f / den[i];
        int row = n0 + 8 * ty + i;
        float4 o;
        o.x = acc[i][0] * inv; o.y = acc[i][1] * inv;
        o.z = acc[i][2] * inv; o.w = acc[i][3] * inv;
        *(float4*)&g_OF[(size_t)(qb * NTOK + row) * DIMV + h * DHEAD + 4 * tx] = o;
    }
}

// ---------------- launch -----------------------------------------------------
extern "C" void kernel_launch(void* const* d_in, const int* in_sizes, int n_in,
                              void* d_out, int out_size) {
    const float* q = (const float*)d_in[0];
    const float* k = (const float*)d_in[1];
    const float* v = (const float*)d_in[2];
    const float* ln_g = (const float*)d_in[3];
    const float* ln_b = (const float*)d_in[4];
    const float* W_in = (const float*)d_in[5];
    const float* wp_W1 = (const float*)d_in[6];
    const float* wp_b1 = (const float*)d_in[7];
    const float* wp_lng = (const float*)d_in[8];
    const float* wp_lnb = (const float*)d_in[9];
    const float* wp_W2 = (const float*)d_in[10];
    const float* wp_b2 = (const float*)d_in[11];
    const float* wp_W3 = (const float*)d_in[12];
    const float* wp_b3 = (const float*)d_in[13];
    const float* wtemp = (const float*)d_in[14];
    const float* W_out = (const float*)d_in[15];
    const float* b_out = (const float*)d_in[16];
    float* out = (float*)d_out;

    float *pXLN, *pF, *pOF;
    cudaGetSymbolAddress((void**)&pXLN, g_XLN);
    cudaGetSymbolAddress((void**)&pF, g_F);
    cudaGetSymbolAddress((void**)&pOF, g_OF);

    cudaFuncSetAttribute(k_softmaxAV, cudaFuncAttributeMaxDynamicSharedMemorySize,
                         SMAV_FLOATS * sizeof(float));

    k_ln<<<NALL, 128>>>(q, k, v, ln_g, ln_b);
    k_mma<<<dim3(DIMV / 128, NALL / 128), 256>>>(pXLN, W_in, nullptr, pF, NALL, DIMV, DIMV);
    k_rowstats<<<8192, 256>>>();
    k_kbar1<<<dim3(NPAIR, 8), 256>>>();
    k_kbar2<<<NPAIR, 64>>>();
    k_ask<<<4096, 256>>>();
    k_qgkg1<<<dim3(NHEAD, 2, 8), 256>>>();
    k_qgkg2<<<dim3(NHEAD, 2), 64>>>();
    k_sstats<<<dim3(8, 8, NPAIR), 256>>>();
    k_rowfinish<<<NHEAD, 256>>>();
    k_finalize<<<1, 32>>>(wp_W1, wp_b1, wp_lng, wp_lnb, wp_W2, wp_b2, wp_W3, wp_b3, wtemp);
    k_softmaxAV<<<dim3(8, NPAIR), 256, SMAV_FLOATS * sizeof(float)>>>();
    k_mma<<<dim3(DIMV / 128, NROWS / 128), 256>>>(pOF, W_out, b_out, out, NROWS, DIMV, DIMV);
}

// round 9
// speedup vs baseline: 1.0453x; 1.0453x over previous
#include <cuda_runtime.h>
#include <math.h>
#include <stdint.h>

#define NTOK 1024
#define DIMV 512
#define NHEAD 8
#define DHEAD 64
#define QBV 4
#define NPAIR 32
#define NROWS 4096
#define NALL 12288
#define NSEG 32768
#define INV8 ((float)(1.0 / (8.0 + 1e-6)))

__device__ float g_XLN[(size_t)NALL * DIMV];
__device__ float g_F[(size_t)NALL * DIMV];
__device__ float g_S[(size_t)NPAIR * NTOK * NTOK];
__device__ float g_OF[(size_t)NROWS * DIMV];
__device__ float g_rncq[NSEG], g_rnsq[NSEG], g_mq[NSEG], g_aq[NSEG];
__device__ float g_rnck[NSEG], g_rnsk[NSEG], g_tk[NSEG], g_sk[NSEG];
__device__ float g_kbar[NPAIR * DHEAD], g_T[NPAIR];
__device__ float g_kpart[NPAIR * 8 * 64];
__device__ float g_qgpart[2 * 8 * 8 * 64];
__device__ float g_qg[NHEAD * DHEAD], g_kg[NHEAD * DHEAD];
__device__ float g_rpart[(size_t)NSEG * 8 * 3];
__device__ double g_mpart[(size_t)NPAIR * 64 * 5];
__device__ double g_mom[NHEAD * 9];
__device__ float g_coef[16];

// ---------------- helpers ---------------------------------------------------
__device__ __forceinline__ uint32_t f2tf32(float x) {
    uint32_t r;
    asm("cvt.rna.tf32.f32 %0, %1;" : "=r"(r) : "f"(x));
    return r;
}
__device__ __forceinline__ void mma_tf32(float* c, const uint32_t* a, uint32_t b0, uint32_t b1) {
    asm volatile(
        "mma.sync.aligned.m16n8k8.row.col.f32.tf32.tf32.f32 "
        "{%0,%1,%2,%3}, {%4,%5,%6,%7}, {%8,%9}, {%0,%1,%2,%3};"
        : "+f"(c[0]), "+f"(c[1]), "+f"(c[2]), "+f"(c[3])
        : "r"(a[0]), "r"(a[1]), "r"(a[2]), "r"(a[3]), "r"(b0), "r"(b1));
}
// packed f32x2 FMA: c += a*b lane-wise (exact fp32 rn)
__device__ __forceinline__ void ffma2(unsigned long long& c, unsigned long long a,
                                      unsigned long long b) {
    asm("fma.rn.f32x2 %0, %1, %2, %0;" : "+l"(c) : "l"(a), "l"(b));
}
// packed f32x2 MUL: c *= a lane-wise (exact fp32 rn)
__device__ __forceinline__ void fmul2(unsigned long long& c, unsigned long long a) {
    asm("mul.rn.f32x2 %0, %0, %1;" : "+l"(c) : "l"(a));
}
__device__ __forceinline__ unsigned long long packdup(float x) {
    unsigned long long r;
    asm("mov.b64 %0, {%1, %1};" : "=l"(r) : "f"(x));
    return r;
}
__device__ __forceinline__ float2 unpack2(unsigned long long v) {
    float2 r;
    asm("mov.b64 {%0, %1}, %2;" : "=f"(r.x), "=f"(r.y) : "l"(v));
    return r;
}

// ---------------- LayerNorm of q,k,v stacked --------------------------------
__global__ void k_ln(const float* __restrict__ q, const float* __restrict__ k,
                     const float* __restrict__ v, const float* __restrict__ g,
                     const float* __restrict__ b) {
    int r = blockIdx.x;
    const float* src = (r < NROWS) ? q + (size_t)r * DIMV
                     : (r < 2 * NROWS) ? k + (size_t)(r - NROWS) * DIMV
                     : v + (size_t)(r - 2 * NROWS) * DIMV;
    int tid = threadIdx.x;  // 128
    float x[4]; float s = 0.f, s2 = 0.f;
#pragma unroll
    for (int j = 0; j < 4; j++) { x[j] = src[tid + j * 128]; s += x[j]; s2 += x[j] * x[j]; }
    __shared__ float shs[4], shs2[4];
    for (int off = 16; off >= 1; off >>= 1) {
        s += __shfl_down_sync(0xffffffffu, s, off);
        s2 += __shfl_down_sync(0xffffffffu, s2, off);
    }
    int lane = tid & 31, w = tid >> 5;
    if (lane == 0) { shs[w] = s; shs2[w] = s2; }
    __syncthreads();
    __shared__ float s_mu, s_rstd;
    if (tid == 0) {
        float S = shs[0] + shs[1] + shs[2] + shs[3];
        float S2 = shs2[0] + shs2[1] + shs2[2] + shs2[3];
        float mu = S / DIMV;
        s_mu = mu; s_rstd = rsqrtf(S2 / DIMV - mu * mu + 1e-5f);
    }
    __syncthreads();
    float mu = s_mu, rstd = s_rstd;
#pragma unroll
    for (int j = 0; j < 4; j++) {
        int c = tid + j * 128;
        g_XLN[(size_t)r * DIMV + c] = (x[j] - mu) * rstd * g[c] + b[c];
    }
}

// ---------------- tf32x3 MMA GEMM: C = A[M,K] @ B[K,N] (+bias) --------------
__global__ __launch_bounds__(256) void k_mma(
        const float* __restrict__ A, const float* __restrict__ B,
        const float* __restrict__ bias, float* __restrict__ C,
        int M, int N, int K) {
    __shared__ float Ah[16][136], Al[16][136], Bh[16][136], Bl[16][136];
    int tid = threadIdx.x;
    int lane = tid & 31, wid = tid >> 5;
    int g = lane >> 2, tg = lane & 3;
    int wm = (wid & 3) * 32, wn = (wid >> 2) * 64;
    int m0 = blockIdx.y * 128, n0 = blockIdx.x * 128;
    int arow = tid & 127, akg = tid >> 7;
    int bng = tid & 31, bk0 = tid >> 5;
    const float* Arow = A + (size_t)(m0 + arow) * K;
    float4 va[2], vb[2];
#pragma unroll
    for (int it = 0; it < 2; it++) {
        va[it] = *(const float4*)&Arow[(akg + 2 * it) * 4];
        vb[it] = *(const float4*)&B[(size_t)(bk0 + 8 * it) * N + n0 + bng * 4];
    }
    float acc[2][8][4];
#pragma unroll
    for (int a = 0; a < 2; a++)
#pragma unroll
        for (int b = 0; b < 8; b++)
#pragma unroll
            for (int c = 0; c < 4; c++) acc[a][b][c] = 0.f;
    for (int kc = 0; kc < K; kc += 16) {
        __syncthreads();
#pragma unroll
        for (int it = 0; it < 2; it++) {
            int kka = (akg + 2 * it) * 4;
            float xs[4] = {va[it].x, va[it].y, va[it].z, va[it].w};
#pragma unroll
            for (int c = 0; c < 4; c++) {
                float hf = __uint_as_float(f2tf32(xs[c]));
                Ah[kka + c][arow] = hf;
                Al[kka + c][arow] = __uint_as_float(f2tf32(xs[c] - hf));
            }
            int kkb = bk0 + 8 * it;
            float ys[4] = {vb[it].x, vb[it].y, vb[it].z, vb[it].w};
            float hb[4], lb[4];
#pragma unroll
            for (int c = 0; c < 4; c++) {
                hb[c] = __uint_as_float(f2tf32(ys[c]));
                lb[c] = __uint_as_float(f2tf32(ys[c] - hb[c]));
            }
            *(float4*)&Bh[kkb][bng * 4] = make_float4(hb[0], hb[1], hb[2], hb[3]);
            *(float4*)&Bl[kkb][bng * 4] = make_float4(lb[0], lb[1], lb[2], lb[3]);
        }
        __syncthreads();
        if (kc + 16 < K) {
            int k0 = kc + 16;
#pragma unroll
            for (int it = 0; it < 2; it++) {
                va[it] = *(const float4*)&Arow[k0 + (akg + 2 * it) * 4];
                vb[it] = *(const float4*)&B[(size_t)(k0 + bk0 + 8 * it) * N + n0 + bng * 4];
            }
        }
#pragma unroll
        for (int ks = 0; ks < 16; ks += 8) {
            uint32_t ah[2][4], al_[2][4];
#pragma unroll
            for (int mt = 0; mt < 2; mt++) {
                int mb = wm + mt * 16 + g;
                ah[mt][0] = __float_as_uint(Ah[ks + tg][mb]);
                ah[mt][1] = __float_as_uint(Ah[ks + tg][mb + 8]);
                ah[mt][2] = __float_as_uint(Ah[ks + tg + 4][mb]);
                ah[mt][3] = __float_as_uint(Ah[ks + tg + 4][mb + 8]);
                al_[mt][0] = __float_as_uint(Al[ks + tg][mb]);
                al_[mt][1] = __float_as_uint(Al[ks + tg][mb + 8]);
                al_[mt][2] = __float_as_uint(Al[ks + tg + 4][mb]);
                al_[mt][3] = __float_as_uint(Al[ks + tg + 4][mb + 8]);
            }
#pragma unroll
            for (int nt = 0; nt < 8; nt++) {
                int nb = wn + nt * 8 + g;
                uint32_t bh0 = __float_as_uint(Bh[ks + tg][nb]);
                uint32_t bh1 = __float_as_uint(Bh[ks + tg + 4][nb]);
                uint32_t bl0 = __float_as_uint(Bl[ks + tg][nb]);
                uint32_t bl1 = __float_as_uint(Bl[ks + tg + 4][nb]);
#pragma unroll
                for (int mt = 0; mt < 2; mt++) {
                    mma_tf32(acc[mt][nt], ah[mt], bh0, bh1);
                    mma_tf32(acc[mt][nt], ah[mt], bl0, bl1);
                    mma_tf32(acc[mt][nt], al_[mt], bh0, bh1);
                }
            }
        }
    }
#pragma unroll
    for (int mt = 0; mt < 2; mt++) {
        int row0 = m0 + wm + mt * 16 + g;
#pragma unroll
        for (int nt = 0; nt < 8; nt++) {
            int col = n0 + wn + nt * 8 + 2 * tg;
            float bx = bias ? bias[col] : 0.f;
            float by = bias ? bias[col + 1] : 0.f;
            *(float2*)&C[(size_t)row0 * N + col] =
                make_float2(acc[mt][nt][0] + bx, acc[mt][nt][1] + by);
            *(float2*)&C[(size_t)(row0 + 8) * N + col] =
                make_float2(acc[mt][nt][2] + bx, acc[mt][nt][3] + by);
        }
    }
}

// ---------------- per (row, head) stats for fq / fk -------------------------
__global__ void k_rowstats() {
    int tid = threadIdx.x;
    int w = tid >> 5, lane = tid & 31;
    int gw = blockIdx.x * 8 + w;
    int tensor = gw >> 15;
    int rem = gw & 32767;
    int row = rem >> 3, h = rem & 7;
    const float* base = &g_F[(size_t)(tensor * NROWS + row) * DIMV + h * DHEAD];
    float v1 = base[lane], v2 = base[lane + 32];
    float s = v1 + v2, sq = v1 * v1 + v2 * v2;
    for (int off = 16; off >= 1; off >>= 1) {
        s += __shfl_down_sync(0xffffffffu, s, off);
        sq += __shfl_down_sync(0xffffffffu, sq, off);
    }
    if (lane == 0) {
        int sidx = h * NROWS + row;
        float nrm = sqrtf(sq);
        if (tensor == 0) {
            g_rncq[sidx] = 1.f / (nrm + 1e-8f);
            g_rnsq[sidx] = 1.f / fmaxf(nrm, 1e-6f);
            g_mq[sidx] = s * (1.f / DHEAD);
        } else {
            g_rnck[sidx] = 1.f / (nrm + 1e-8f);
            g_rnsk[sidx] = 1.f / fmaxf(nrm, 1e-6f);
            g_tk[sidx] = s;
        }
    }
}

// ---------------- kbar two-stage --------------------------------------------
__global__ void k_kbar1() {
    int p = blockIdx.x, seg = blockIdx.y;
    int h = p >> 2, qb = p & 3;
    int tid = threadIdx.x, d = tid & 63, rr = tid >> 6;
    float acc = 0.f;
    int base = qb * NTOK + seg * 128;
    for (int m = rr; m < 128; m += 4)
        acc += g_F[(size_t)(NROWS + base + m) * DIMV + h * DHEAD + d];
    __shared__ float red[256];
    red[tid] = acc;
    __syncthreads();
    if (rr == 0) g_kpart[(p * 8 + seg) * 64 + d] = red[d] + red[64 + d] + red[128 + d] + red[192 + d];
}
__global__ void k_kbar2() {
    int p = blockIdx.x, d = threadIdx.x;
    float s = 0.f;
    for (int seg = 0; seg < 8; seg++) s += g_kpart[(p * 8 + seg) * 64 + d];
    float kb = s * (1.f / NTOK);
    g_kbar[p * DHEAD + d] = kb;
    __shared__ float sh[64];
    sh[d] = kb;
    __syncthreads();
    if (d == 0) {
        float t = 0.f;
        for (int i = 0; i < 64; i++) t += sh[i];
        g_T[p] = t;
    }
}

// ---------------- a[n] = fq . kbar ; sk[m] = tk[m] - T ----------------------
__global__ void k_ask() {
    int tid = threadIdx.x, w = tid >> 5, lane = tid & 31;
    int t = blockIdx.x * 8 + w;
    int p = t >> 10, n = t & 1023;
    int h = p >> 2, qb = p & 3;
    const float* fq = &g_F[(size_t)(qb * NTOK + n) * DIMV + h * DHEAD];
    const float* kb = &g_kbar[p * DHEAD];
    float s = fq[lane] * kb[lane] + fq[lane + 32] * kb[lane + 32];
    for (int off = 16; off >= 1; off >>= 1) s += __shfl_down_sync(0xffffffffu, s, off);
    if (lane == 0) { g_aq[t] = s; g_sk[t] = g_tk[t] - g_T[p]; }
}

// ---------------- qg/kg two-stage -------------------------------------------
__global__ void k_qgkg1() {
    int h = blockIdx.x, tensor = blockIdx.y, seg = blockIdx.z;
    int tid = threadIdx.x, d = tid & 63, rr = tid >> 6;
    float acc = 0.f;
    for (int r = rr; r < 512; r += 4)
        acc += g_F[(size_t)(tensor * NROWS + seg * 512 + r) * DIMV + h * DHEAD + d];
    __shared__ float red[256];
    red[tid] = acc;
    __syncthreads();
    if (rr == 0)
        g_qgpart[((tensor * 8 + h) * 8 + seg) * 64 + d] = red[d] + red[64 + d] + red[128 + d] + red[192 + d];
}
__global__ void k_qgkg2() {
    int h = blockIdx.x, tensor = blockIdx.y, d = threadIdx.x;
    float s = 0.f;
    for (int seg = 0; seg < 8; seg++) s += g_qgpart[((tensor * 8 + h) * 8 + seg) * 64 + d];
    (tensor == 0 ? g_qg : g_kg)[h * 64 + d] = s * (1.f / NROWS);
}

// ---------------- S = fq @ fk^T (128x128, packed f32x2 FMA) + moments -------
__global__ __launch_bounds__(256) void k_sstats() {
    int p = blockIdx.z, h = p >> 2, qb = p & 3;
    int n0 = blockIdx.y * 128, m0 = blockIdx.x * 128;
    __shared__ float Aq[32][132];
    __shared__ float Bk[32][132];
    __shared__ float rowv[4][128];
    __shared__ float colv[3][128];
    __shared__ float wsum[8];
    int tid = threadIdx.x;
    int tx = tid & 15, ty = tid >> 4;
    int lrow = tid & 127, lkg0 = tid >> 7;
    const float* qsrc = &g_F[(size_t)(qb * NTOK + n0 + lrow) * DIMV + h * DHEAD];
    const float* ksrc = &g_F[(size_t)(NROWS + qb * NTOK + m0 + lrow) * DIMV + h * DHEAD];
    if (tid < 128) {
        int sr = p * NTOK + n0 + tid;
        rowv[0][tid] = g_rncq[sr]; rowv[1][tid] = g_rnsq[sr];
        rowv[2][tid] = g_aq[sr];   rowv[3][tid] = g_mq[sr];
        int sc = p * NTOK + m0 + tid;
        colv[0][tid] = g_rnck[sc]; colv[1][tid] = g_rnsk[sc]; colv[2][tid] = g_sk[sc];
    }
    float4 va[4], vb[4];
    int kc = 0;
#pragma unroll
    for (int it = 0; it < 4; it++) {
        va[it] = *(const float4*)&qsrc[kc + (lkg0 + 2 * it) * 4];
        vb[it] = *(const float4*)&ksrc[kc + (lkg0 + 2 * it) * 4];
    }
    unsigned long long accp[8][4];
#pragma unroll
    for (int i = 0; i < 8; i++)
#pragma unroll
        for (int jp = 0; jp < 4; jp++) accp[i][jp] = 0ull;
    for (int c = 0; c < 2; c++) {
        __syncthreads();
#pragma unroll
        for (int it = 0; it < 4; it++) {
            int kg = (lkg0 + 2 * it) * 4;
            Aq[kg + 0][lrow] = va[it].x; Aq[kg + 1][lrow] = va[it].y;
            Aq[kg + 2][lrow] = va[it].z; Aq[kg + 3][lrow] = va[it].w;
            Bk[kg + 0][lrow] = vb[it].x; Bk[kg + 1][lrow] = vb[it].y;
            Bk[kg + 2][lrow] = vb[it].z; Bk[kg + 3][lrow] = vb[it].w;
        }
        __syncthreads();
        if (c == 0) {
            kc = 32;
#pragma unroll
            for (int it = 0; it < 4; it++) {
                va[it] = *(const float4*)&qsrc[kc + (lkg0 + 2 * it) * 4];
                vb[it] = *(const float4*)&ksrc[kc + (lkg0 + 2 * it) * 4];
            }
        }
#pragma unroll
        for (int kk = 0; kk < 32; kk++) {
            float4 a0 = *(float4*)&Aq[kk][8 * ty];
            float4 a1 = *(float4*)&Aq[kk][8 * ty + 4];
            ulonglong2 b01 = *(ulonglong2*)&Bk[kk][8 * tx];
            ulonglong2 b23 = *(ulonglong2*)&Bk[kk][8 * tx + 4];
            float av[8] = {a0.x, a0.y, a0.z, a0.w, a1.x, a1.y, a1.z, a1.w};
#pragma unroll
            for (int i = 0; i < 8; i++) {
                unsigned long long ap = packdup(av[i]);
                ffma2(accp[i][0], ap, b01.x);
                ffma2(accp[i][1], ap, b01.y);
                ffma2(accp[i][2], ap, b23.x);
                ffma2(accp[i][3], ap, b23.y);
            }
        }
    }
    float acc[8][8];
#pragma unroll
    for (int i = 0; i < 8; i++)
#pragma unroll
        for (int jp = 0; jp < 4; jp++) {
            float2 u = unpack2(accp[i][jp]);
            acc[i][2 * jp] = u.x; acc[i][2 * jp + 1] = u.y;
        }
    float tc = 0.f, tc2 = 0.f, tp = 0.f, tp2 = 0.f, tcp = 0.f;
    size_t sbase = ((size_t)p << 20);
#pragma unroll
    for (int i = 0; i < 8; i++) {
        int row = 8 * ty + i;
        float rq = rowv[0][row], rsq = rowv[1][row];
        float aqv = rowv[2][row], mqv = rowv[3][row];
        float vc = 0.f, vp = 0.f, vm = 0.f;
        float st[8];
#pragma unroll
        for (int j = 0; j < 8; j++) {
            int col = 8 * tx + j;
            float sv = acc[i][j];
            float cosv = fminf(fmaxf(sv * rq * colv[0][col], -0.99f), 0.99f);
            float csim = fminf(fmaxf(sv * rsq * colv[1][col], -0.99f), 0.99f);
            float mar = fminf(fmaxf(0.01f - csim, 0.f), 10.f);
            float pre = (sv - aqv - mqv * colv[2][col]) * INV8;
            tc += cosv; tc2 += cosv * cosv;
            tp += pre;  tp2 += pre * pre; tcp += cosv * pre;
            vc += cosv; vp += pre; vm += mar;
            st[j] = sv;
        }
        size_t so = sbase + (size_t)(n0 + row) * NTOK + m0 + 8 * tx;
        *(float4*)&g_S[so] = make_float4(st[0], st[1], st[2], st[3]);
        *(float4*)&g_S[so + 4] = make_float4(st[4], st[5], st[6], st[7]);
        for (int off = 8; off >= 1; off >>= 1) {
            vc += __shfl_xor_sync(0xffffffffu, vc, off, 16);
            vp += __shfl_xor_sync(0xffffffffu, vp, off, 16);
            vm += __shfl_xor_sync(0xffffffffu, vm, off, 16);
        }
        if (tx == 0) {
            size_t s = (size_t)(p * NTOK + n0 + row) * 8 + blockIdx.x;
            g_rpart[s * 3 + 0] = vc; g_rpart[s * 3 + 1] = vp; g_rpart[s * 3 + 2] = vm;
        }
    }
    float vals[5] = {tc, tc2, tp, tp2, tcp};
    int lane = tid & 31, w = tid >> 5;
    for (int v = 0; v < 5; v++) {
        float x = vals[v];
        for (int off = 16; off >= 1; off >>= 1) x += __shfl_down_sync(0xffffffffu, x, off);
        if (lane == 0) wsum[w] = x;
        __syncthreads();
        if (tid == 0) {
            float s = 0.f;
            for (int i = 0; i < 8; i++) s += wsum[i];
            g_mpart[(size_t)(p * 64 + blockIdx.y * 8 + blockIdx.x) * 5 + v] = (double)s;
        }
        __syncthreads();
    }
}

// ---------------- per-head reductions: rows + moments -----------------------
__global__ void k_rowfinish() {
    int h = blockIdx.x, tid = threadIdx.x;
    double a5 = 0, a6 = 0, a7 = 0, a8 = 0;
    for (int r = tid; r < NROWS; r += 256) {
        int s = h * NROWS + r;
        float rc = 0.f, rp = 0.f, rm = 0.f;
        for (int mb = 0; mb < 8; mb++) {
            size_t idx = ((size_t)s * 8 + mb) * 3;
            rc += g_rpart[idx]; rp += g_rpart[idx + 1]; rm += g_rpart[idx + 2];
        }
        double v = (double)rm * (1.0 / 1024.0);
        a5 += 1024.0 * v; a6 += 1024.0 * v * v;
        a7 += v * (double)rc; a8 += v * (double)rp;
    }
    __shared__ double sh[256];
    double vals[4] = {a5, a6, a7, a8};
    for (int v = 0; v < 4; v++) {
        sh[tid] = vals[v];
        __syncthreads();
        for (int s = 128; s >= 1; s >>= 1) {
            if (tid < s) sh[tid] += sh[tid + s];
            __syncthreads();
        }
        if (tid == 0) g_mom[h * 9 + 5 + v] = sh[0];
        __syncthreads();
    }
    for (int v = 0; v < 5; v++) {
        int qb = tid >> 6, blk = tid & 63;
        sh[tid] = g_mpart[(size_t)((h * 4 + qb) * 64 + blk) * 5 + v];
        __syncthreads();
        for (int s = 128; s >= 1; s >>= 1) {
            if (tid < s) sh[tid] += sh[tid + s];
            __syncthreads();
        }
        if (tid == 0) g_mom[h * 9 + v] = sh[0];
        __syncthreads();
    }
}

__device__ double dev_std(double s, double s2, double N) {
    double v = (s2 - s * s / N) / (N - 1.0);
    return v > 0.0 ? sqrt(v) : 0.0;
}

// ---------------- finalize: MLP weights + global scalars --------------------
__global__ void k_finalize(const float* __restrict__ W1, const float* __restrict__ b1,
                           const float* __restrict__ lng, const float* __restrict__ lnb,
                           const float* __restrict__ W2, const float* __restrict__ b2,
                           const float* __restrict__ W3, const float* __restrict__ b3,
                           const float* __restrict__ wtp) {
    __shared__ float ws[8][3];
    int tid = threadIdx.x;
    if (tid < 8) {
        int h = tid;
        float y[64];
        for (int i = 0; i < 64; i++) {
            float a = b1[i];
            for (int j = 0; j < 64; j++) a += g_qg[h * 64 + j] * W1[j * 64 + i];
            for (int j = 0; j < 64; j++) a += g_kg[h * 64 + j] * W1[(64 + j) * 64 + i];
            y[i] = a;
        }
        float mu = 0.f;
        for (int i = 0; i < 64; i++) mu += y[i];
        mu *= (1.f / 64.f);
        float var = 0.f;
        for (int i = 0; i < 64; i++) { float d = y[i] - mu; var += d * d; }
        float rstd = rsqrtf(var * (1.f / 64.f) + 1e-5f);
        for (int i = 0; i < 64; i++)
            y[i] = fmaxf((y[i] - mu) * rstd * lng[i] + lnb[i], 0.f);
        float hh[32];
        for (int o = 0; o < 32; o++) {
            float a = b2[o];
            for (int i = 0; i < 64; i++) a += y[i] * W2[i * 32 + o];
            hh[o] = fmaxf(a, 0.f);
        }
        float l[3];
        for (int c = 0; c < 3; c++) {
            float a = b3[c];
            for (int o = 0; o < 32; o++) a += hh[o] * W3[o * 3 + c];
            l[c] = a;
        }
        float mx = fmaxf(l[0], fmaxf(l[1], l[2]));
        float e0 = expf(l[0] - mx), e1 = expf(l[1] - mx), e2 = expf(l[2] - mx);
        float sm = e0 + e1 + e2;
        l[0] = e0 / sm; l[1] = e1 / sm; l[2] = e2 / sm;
        float wt = fminf(fmaxf(wtp[0], 0.1f), 20.f);
        l[0] /= wt; l[1] /= wt; l[2] /= wt;
        mx = fmaxf(l[0], fmaxf(l[1], l[2]));
        e0 = expf(l[0] - mx); e1 = expf(l[1] - mx); e2 = expf(l[2] - mx);
        sm = e0 + e1 + e2;
        l[0] = e0 / sm; l[1] = e1 / sm; l[2] = e2 / sm;
        for (int c = 0; c < 3; c++) l[c] = fminf(fmaxf(l[c], 0.05f), 0.8f);
        sm = l[0] + l[1] + l[2];
        ws[h][0] = l[0] / sm; ws[h][1] = l[1] / sm; ws[h][2] = l[2] / sm;
    }
    __syncthreads();
    if (tid == 0) {
        const double N = 33554432.0;
        double Sc = 0, Sc2 = 0, Sp = 0, Sp2 = 0, Sv = 0, Sv2 = 0;
        for (int h = 0; h < 8; h++) {
            Sc += g_mom[h * 9 + 0]; Sc2 += g_mom[h * 9 + 1];
            Sp += g_mom[h * 9 + 2]; Sp2 += g_mom[h * 9 + 3];
            Sv += g_mom[h * 9 + 5]; Sv2 += g_mom[h * 9 + 6];
        }
        double cstd = dev_std(Sc, Sc2, N);
        double pstd = dev_std(Sp, Sp2, N);
        double vstd = dev_std(Sv, Sv2, N);
        double base = 0.001 / 1024.0;
        double reg = (pstd < 1e-6) ? base * 10.0 : base;
        double cn = cstd + 1e-6;
        double covn = reg * pstd + 1e-6;
        double vn = vstd + 1e-6;
        double cscale = (cn < 1e-4) ? 0.1 : 1.0;
        double Sd = 0, Sd2 = 0, al[8], be[8];
        for (int h = 0; h < 8; h++) {
            double a = (double)ws[h][0] * cscale / cn;
            double bb = (double)ws[h][1] * 0.5 / covn;
            double gg = (double)ws[h][2] * 0.5 / vn;
            al[h] = a; be[h] = bb;
            double m0 = g_mom[h * 9 + 0], m1 = g_mom[h * 9 + 1];
            double m2 = g_mom[h * 9 + 2], m3 = g_mom[h * 9 + 3];
            double m4 = g_mom[h * 9 + 4], m5 = g_mom[h * 9 + 5];
            double m6 = g_mom[h * 9 + 6], m7 = g_mom[h * 9 + 7];
            double m8 = g_mom[h * 9 + 8];
            Sd += a * m0 + bb * reg * m2 + gg * m5;
            Sd2 += a * a * m1 + bb * bb * reg * reg * m3 + gg * gg * m6
                 + 2.0 * a * bb * reg * m4 + 2.0 * a * gg * m7 + 2.0 * bb * gg * reg * m8;
        }
        double dvar = (Sd2 - Sd * Sd / N) / (N - 1.0);
        double dstd = dvar > 0.0 ? sqrt(dvar) : 0.0;
        double temp = (dstd < 1e-6) ? 0.1 : 0.3 + dstd;
        temp = fmin(fmax(temp, 0.1), 5.0);
        for (int h = 0; h < 8; h++) {
            g_coef[h] = (float)(al[h] / temp);
            g_coef[8 + h] = (float)(be[h] * reg / temp);
        }
    }
}

// ---------------- online softmax + AV (packed f32x2 AV phase) ---------------
#define VS_PITCH 68
#define PS_PITCH 69
#define SMAV_FLOATS (64 * VS_PITCH + 128 * PS_PITCH + 128 * 3 + 64 * 2)
__global__ __launch_bounds__(256) void k_softmaxAV() {
    extern __shared__ float smp[];
    float (*Vs)[VS_PITCH] = (float(*)[VS_PITCH])smp;
    float (*Ps)[PS_PITCH] = (float(*)[PS_PITCH])(smp + 64 * VS_PITCH);
    float* rq = smp + 64 * VS_PITCH + 128 * PS_PITCH;
    float* aqv = rq + 128;
    float* mqv = aqv + 128;
    float* rk = mqv + 128;
    float* skv = rk + 64;
    int p = blockIdx.y, h = p >> 2, qb = p & 3;
    int n0 = blockIdx.x * 128;
    int tid = threadIdx.x;
    int tx = tid & 15, ty = tid >> 4;
    float cA = g_coef[h], cB = g_coef[8 + h];
    if (tid < 128) {
        int s = p * NTOK + n0 + tid;
        rq[tid] = g_rncq[s]; aqv[tid] = g_aq[s]; mqv[tid] = g_mq[s];
    }
    unsigned long long accp[8][2];
#pragma unroll
    for (int i = 0; i < 8; i++) { accp[i][0] = 0ull; accp[i][1] = 0ull; }
    float rmax[8], den[8] = {};
#pragma unroll
    for (int i = 0; i < 8; i++) rmax[i] = -1e30f;
    size_t sbase = ((size_t)p << 20);
    for (int mt = 0; mt < 16; mt++) {
        int m0 = mt * 64;
        __syncthreads();
#pragma unroll
        for (int it = 0; it < 4; it++) {
            int lin = tid + it * 256;
            int r = lin >> 4, ks = (lin & 15) * 4;
            float4 v4 = *(const float4*)&g_F[(size_t)(2 * NROWS + qb * NTOK + m0 + r) * DIMV + h * DHEAD + ks];
            Vs[r][ks + 0] = v4.x; Vs[r][ks + 1] = v4.y; Vs[r][ks + 2] = v4.z; Vs[r][ks + 3] = v4.w;
        }
        if (tid < 64) {
            int s = p * NTOK + m0 + tid;
            rk[tid] = g_rnck[s]; skv[tid] = g_sk[s];
        }
        __syncthreads();
#pragma unroll
        for (int i = 0; i < 8; i++) {
            int row = 8 * ty + i;
            float4 s4 = *(const float4*)&g_S[sbase + (size_t)(n0 + row) * NTOK + m0 + 4 * tx];
            float rr = rq[row], av = aqv[row], mv = mqv[row];
            float z[4];
#pragma unroll
            for (int j = 0; j < 4; j++) {
                int col = 4 * tx + j;
                float sv = (&s4.x)[j];
                float cosv = fminf(fmaxf(sv * rr * rk[col], -0.99f), 0.99f);
                float pre = (sv - av - mv * skv[col]) * INV8;
                z[j] = cA * cosv + cB * pre;
            }
            float tm = fmaxf(fmaxf(z[0], z[1]), fmaxf(z[2], z[3]));
            for (int off = 8; off >= 1; off >>= 1)
                tm = fmaxf(tm, __shfl_xor_sync(0xffffffffu, tm, off, 16));
            float nm = fmaxf(rmax[i], tm);
            float corr = __expf(rmax[i] - nm);
            float ps = 0.f;
#pragma unroll
            for (int j = 0; j < 4; j++) {
                float pv = __expf(z[j] - nm);
                Ps[row][4 * tx + j] = pv;
                ps += pv;
            }
            for (int off = 8; off >= 1; off >>= 1)
                ps += __shfl_xor_sync(0xffffffffu, ps, off, 16);
            den[i] = den[i] * corr + ps;
            rmax[i] = nm;
            unsigned long long cp = packdup(corr);
            fmul2(accp[i][0], cp);   // acc *= corr (lane-wise mul.rn.f32x2)
            fmul2(accp[i][1], cp);
        }
        __syncthreads();
#pragma unroll 4
        for (int m = 0; m < 64; m++) {
            ulonglong2 v2 = *(ulonglong2*)&Vs[m][4 * tx];
#pragma unroll
            for (int i = 0; i < 8; i++) {
                unsigned long long pp = packdup(Ps[8 * ty + i][m]);
                ffma2(accp[i][0], pp, v2.x);
                ffma2(accp[i][1], pp, v2.y);
            }
        }
    }
#pragma unroll
    for (int i = 0; i < 8; i++) {
        float inv = 1.f / den[i];
        int row = n0 + 8 * ty + i;
        float2 u0 = unpack2(accp[i][0]);
        float2 u1 = unpack2(accp[i][1]);
        float4 o;
        o.x = u0.x * inv; o.y = u0.y * inv;
        o.z = u1.x * inv; o.w = u1.y * inv;
        *(float4*)&g_OF[(size_t)(qb * NTOK + row) * DIMV + h * DHEAD + 4 * tx] = o;
    }
}

// ---------------- launch -----------------------------------------------------
extern "C" void kernel_launch(void* const* d_in, const int* in_sizes, int n_in,
                              void* d_out, int out_size) {
    const float* q = (const float*)d_in[0];
    const float* k = (const float*)d_in[1];
    const float* v = (const float*)d_in[2];
    const float* ln_g = (const float*)d_in[3];
    const float* ln_b = (const float*)d_in[4];
    const float* W_in = (const float*)d_in[5];
    const float* wp_W1 = (const float*)d_in[6];
    const float* wp_b1 = (const float*)d_in[7];
    const float* wp_lng = (const float*)d_in[8];
    const float* wp_lnb = (const float*)d_in[9];
    const float* wp_W2 = (const float*)d_in[10];
    const float* wp_b2 = (const float*)d_in[11];
    const float* wp_W3 = (const float*)d_in[12];
    const float* wp_b3 = (const float*)d_in[13];
    const float* wtemp = (const float*)d_in[14];
    const float* W_out = (const float*)d_in[15];
    const float* b_out = (const float*)d_in[16];
    float* out = (float*)d_out;

    float *pXLN, *pF, *pOF;
    cudaGetSymbolAddress((void**)&pXLN, g_XLN);
    cudaGetSymbolAddress((void**)&pF, g_F);
    cudaGetSymbolAddress((void**)&pOF, g_OF);

    cudaFuncSetAttribute(k_softmaxAV, cudaFuncAttributeMaxDynamicSharedMemorySize,
                         SMAV_FLOATS * sizeof(float));

    k_ln<<<NALL, 128>>>(q, k, v, ln_g, ln_b);
    k_mma<<<dim3(DIMV / 128, NALL / 128), 256>>>(pXLN, W_in, nullptr, pF, NALL, DIMV, DIMV);
    k_rowstats<<<8192, 256>>>();
    k_kbar1<<<dim3(NPAIR, 8), 256>>>();
    k_kbar2<<<NPAIR, 64>>>();
    k_ask<<<4096, 256>>>();
    k_qgkg1<<<dim3(NHEAD, 2, 8), 256>>>();
    k_qgkg2<<<dim3(NHEAD, 2), 64>>>();
    k_sstats<<<dim3(8, 8, NPAIR), 256>>>();
    k_rowfinish<<<NHEAD, 256>>>();
    k_finalize<<<1, 32>>>(wp_W1, wp_b1, wp_lng, wp_lnb, wp_W2, wp_b2, wp_W3, wp_b3, wtemp);
    k_softmaxAV<<<dim3(8, NPAIR), 256, SMAV_FLOATS * sizeof(float)>>>();
    k_mma<<<dim3(DIMV / 128, NROWS / 128), 256>>>(pOF, W_out, b_out, out, NROWS, DIMV, DIMV);
}

// round 13
// speedup vs baseline: 1.1014x; 1.0536x over previous
#include <cuda_runtime.h>
#include <math.h>
#include <stdint.h>

#define NTOK 1024
#define DIMV 512
#define NHEAD 8
#define DHEAD 64
#define QBV 4
#define NPAIR 32
#define NROWS 4096
#define NALL 12288
#define NSEG 32768
#define INV8 ((float)(1.0 / (8.0 + 1e-6)))

__device__ float g_XLN[(size_t)NALL * DIMV];
__device__ float g_F[(size_t)NALL * DIMV];
__device__ float g_S[(size_t)NPAIR * NTOK * NTOK];
__device__ float g_OF[(size_t)NROWS * DIMV];
__device__ float g_rncq[NSEG], g_rnsq[NSEG], g_mq[NSEG], g_aq[NSEG];
__device__ float g_rnck[NSEG], g_rnsk[NSEG], g_tk[NSEG], g_sk[NSEG];
__device__ float g_kbar[NPAIR * DHEAD], g_T[NPAIR];
__device__ float g_kpart[NPAIR * 8 * 64];
__device__ float g_qgpart[2 * 8 * 8 * 64];
__device__ float g_qg[NHEAD * DHEAD], g_kg[NHEAD * DHEAD];
__device__ float g_rpart[(size_t)NSEG * 8 * 3];
__device__ double g_mpart[(size_t)NPAIR * 64 * 5];
__device__ double g_mom[NHEAD * 9];
__device__ float g_coef[16];

// ---------------- helpers ---------------------------------------------------
__device__ __forceinline__ uint32_t f2tf32(float x) {
    uint32_t r;
    asm("cvt.rna.tf32.f32 %0, %1;" : "=r"(r) : "f"(x));
    return r;
}
__device__ __forceinline__ void mma_tf32(float* c, const uint32_t* a, uint32_t b0, uint32_t b1) {
    asm volatile(
        "mma.sync.aligned.m16n8k8.row.col.f32.tf32.tf32.f32 "
        "{%0,%1,%2,%3}, {%4,%5,%6,%7}, {%8,%9}, {%0,%1,%2,%3};"
        : "+f"(c[0]), "+f"(c[1]), "+f"(c[2]), "+f"(c[3])
        : "r"(a[0]), "r"(a[1]), "r"(a[2]), "r"(a[3]), "r"(b0), "r"(b1));
}
__device__ __forceinline__ void ffma2(unsigned long long& c, unsigned long long a,
                                      unsigned long long b) {
    asm("fma.rn.f32x2 %0, %1, %2, %0;" : "+l"(c) : "l"(a), "l"(b));
}
__device__ __forceinline__ void fmul2(unsigned long long& c, unsigned long long a) {
    asm("mul.rn.f32x2 %0, %0, %1;" : "+l"(c) : "l"(a));
}
__device__ __forceinline__ unsigned long long packdup(float x) {
    unsigned long long r;
    asm("mov.b64 %0, {%1, %1};" : "=l"(r) : "f"(x));
    return r;
}
__device__ __forceinline__ float2 unpack2(unsigned long long v) {
    float2 r;
    asm("mov.b64 {%0, %1}, %2;" : "=f"(r.x), "=f"(r.y) : "l"(v));
    return r;
}

// ---------------- LayerNorm of q,k,v stacked --------------------------------
__global__ void k_ln(const float* __restrict__ q, const float* __restrict__ k,
                     const float* __restrict__ v, const float* __restrict__ g,
                     const float* __restrict__ b) {
    int r = blockIdx.x;
    const float* src = (r < NROWS) ? q + (size_t)r * DIMV
                     : (r < 2 * NROWS) ? k + (size_t)(r - NROWS) * DIMV
                     : v + (size_t)(r - 2 * NROWS) * DIMV;
    int tid = threadIdx.x;  // 128
    float x[4]; float s = 0.f, s2 = 0.f;
#pragma unroll
    for (int j = 0; j < 4; j++) { x[j] = src[tid + j * 128]; s += x[j]; s2 += x[j] * x[j]; }
    __shared__ float shs[4], shs2[4];
    for (int off = 16; off >= 1; off >>= 1) {
        s += __shfl_down_sync(0xffffffffu, s, off);
        s2 += __shfl_down_sync(0xffffffffu, s2, off);
    }
    int lane = tid & 31, w = tid >> 5;
    if (lane == 0) { shs[w] = s; shs2[w] = s2; }
    __syncthreads();
    __shared__ float s_mu, s_rstd;
    if (tid == 0) {
        float S = shs[0] + shs[1] + shs[2] + shs[3];
        float S2 = shs2[0] + shs2[1] + shs2[2] + shs2[3];
        float mu = S / DIMV;
        s_mu = mu; s_rstd = rsqrtf(S2 / DIMV - mu * mu + 1e-5f);
    }
    __syncthreads();
    float mu = s_mu, rstd = s_rstd;
#pragma unroll
    for (int j = 0; j < 4; j++) {
        int c = tid + j * 128;
        g_XLN[(size_t)r * DIMV + c] = (x[j] - mu) * rstd * g[c] + b[c];
    }
}

// ---------------- tf32x2 MMA GEMM: C = A[M,K] @ B[K,N] (+bias) --------------
__global__ __launch_bounds__(256) void k_mma(
        const float* __restrict__ A, const float* __restrict__ B,
        const float* __restrict__ bias, float* __restrict__ C,
        int M, int N, int K) {
    __shared__ float Ah[16][136], Bh[16][136], Bl[16][136];
    int tid = threadIdx.x;
    int lane = tid & 31, wid = tid >> 5;
    int g = lane >> 2, tg = lane & 3;
    int wm = (wid & 3) * 32, wn = (wid >> 2) * 64;
    int m0 = blockIdx.y * 128, n0 = blockIdx.x * 128;
    int arow = tid & 127, akg = tid >> 7;
    int bng = tid & 31, bk0 = tid >> 5;
    const float* Arow = A + (size_t)(m0 + arow) * K;
    float4 va[2], vb[2];
#pragma unroll
    for (int it = 0; it < 2; it++) {
        va[it] = *(const float4*)&Arow[(akg + 2 * it) * 4];
        vb[it] = *(const float4*)&B[(size_t)(bk0 + 8 * it) * N + n0 + bng * 4];
    }
    float acc[2][8][4];
#pragma unroll
    for (int a = 0; a < 2; a++)
#pragma unroll
        for (int b = 0; b < 8; b++)
#pragma unroll
            for (int c = 0; c < 4; c++) acc[a][b][c] = 0.f;
    for (int kc = 0; kc < K; kc += 16) {
        __syncthreads();
#pragma unroll
        for (int it = 0; it < 2; it++) {
            int kka = (akg + 2 * it) * 4;
            float xs[4] = {va[it].x, va[it].y, va[it].z, va[it].w};
#pragma unroll
            for (int c = 0; c < 4; c++)
                Ah[kka + c][arow] = __uint_as_float(f2tf32(xs[c]));
            int kkb = bk0 + 8 * it;
            float ys[4] = {vb[it].x, vb[it].y, vb[it].z, vb[it].w};
            float hb[4], lb[4];
#pragma unroll
            for (int c = 0; c < 4; c++) {
                hb[c] = __uint_as_float(f2tf32(ys[c]));
                lb[c] = __uint_as_float(f2tf32(ys[c] - hb[c]));
            }
            *(float4*)&Bh[kkb][bng * 4] = make_float4(hb[0], hb[1], hb[2], hb[3]);
            *(float4*)&Bl[kkb][bng * 4] = make_float4(lb[0], lb[1], lb[2], lb[3]);
        }
        __syncthreads();
        if (kc + 16 < K) {
            int k0 = kc + 16;
#pragma unroll
            for (int it = 0; it < 2; it++) {
                va[it] = *(const float4*)&Arow[k0 + (akg + 2 * it) * 4];
                vb[it] = *(const float4*)&B[(size_t)(k0 + bk0 + 8 * it) * N + n0 + bng * 4];
            }
        }
#pragma unroll
        for (int ks = 0; ks < 16; ks += 8) {
            uint32_t ah[2][4];
#pragma unroll
            for (int mt = 0; mt < 2; mt++) {
                int mb = wm + mt * 16 + g;
                ah[mt][0] = __float_as_uint(Ah[ks + tg][mb]);
                ah[mt][1] = __float_as_uint(Ah[ks + tg][mb + 8]);
                ah[mt][2] = __float_as_uint(Ah[ks + tg + 4][mb]);
                ah[mt][3] = __float_as_uint(Ah[ks + tg + 4][mb + 8]);
            }
#pragma unroll
            for (int nt = 0; nt < 8; nt++) {
                int nb = wn + nt * 8 + g;
                uint32_t bh0 = __float_as_uint(Bh[ks + tg][nb]);
                uint32_t bh1 = __float_as_uint(Bh[ks + tg + 4][nb]);
                uint32_t bl0 = __float_as_uint(Bl[ks + tg][nb]);
                uint32_t bl1 = __float_as_uint(Bl[ks + tg + 4][nb]);
#pragma unroll
                for (int mt = 0; mt < 2; mt++) {
                    mma_tf32(acc[mt][nt], ah[mt], bh0, bh1);
                    mma_tf32(acc[mt][nt], ah[mt], bl0, bl1);
                }
            }
        }
    }
#pragma unroll
    for (int mt = 0; mt < 2; mt++) {
        int row0 = m0 + wm + mt * 16 + g;
#pragma unroll
        for (int nt = 0; nt < 8; nt++) {
            int col = n0 + wn + nt * 8 + 2 * tg;
            float bx = bias ? bias[col] : 0.f;
            float by = bias ? bias[col + 1] : 0.f;
            *(float2*)&C[(size_t)row0 * N + col] =
                make_float2(acc[mt][nt][0] + bx, acc[mt][nt][1] + by);
            *(float2*)&C[(size_t)(row0 + 8) * N + col] =
                make_float2(acc[mt][nt][2] + bx, acc[mt][nt][3] + by);
        }
    }
}

// ---------------- per (row, head) stats for fq / fk -------------------------
__global__ void k_rowstats() {
    int tid = threadIdx.x;
    int w = tid >> 5, lane = tid & 31;
    int gw = blockIdx.x * 8 + w;
    int tensor = gw >> 15;
    int rem = gw & 32767;
    int row = rem >> 3, h = rem & 7;
    const float* base = &g_F[(size_t)(tensor * NROWS + row) * DIMV + h * DHEAD];
    float v1 = base[lane], v2 = base[lane + 32];
    float s = v1 + v2, sq = v1 * v1 + v2 * v2;
    for (int off = 16; off >= 1; off >>= 1) {
        s += __shfl_down_sync(0xffffffffu, s, off);
        sq += __shfl_down_sync(0xffffffffu, sq, off);
    }
    if (lane == 0) {
        int sidx = h * NROWS + row;
        float nrm = sqrtf(sq);
        if (tensor == 0) {
            g_rncq[sidx] = 1.f / (nrm + 1e-8f);
            g_rnsq[sidx] = 1.f / fmaxf(nrm, 1e-6f);
            g_mq[sidx] = s * (1.f / DHEAD);
        } else {
            g_rnck[sidx] = 1.f / (nrm + 1e-8f);
            g_rnsk[sidx] = 1.f / fmaxf(nrm, 1e-6f);
            g_tk[sidx] = s;
        }
    }
}

// ---------------- kbar two-stage --------------------------------------------
__global__ void k_kbar1() {
    int p = blockIdx.x, seg = blockIdx.y;
    int h = p >> 2, qb = p & 3;
    int tid = threadIdx.x, d = tid & 63, rr = tid >> 6;
    float acc = 0.f;
    int base = qb * NTOK + seg * 128;
    for (int m = rr; m < 128; m += 4)
        acc += g_F[(size_t)(NROWS + base + m) * DIMV + h * DHEAD + d];
    __shared__ float red[256];
    red[tid] = acc;
    __syncthreads();
    if (rr == 0) g_kpart[(p * 8 + seg) * 64 + d] = red[d] + red[64 + d] + red[128 + d] + red[192 + d];
}
__global__ void k_kbar2() {
    int p = blockIdx.x, d = threadIdx.x;
    float s = 0.f;
    for (int seg = 0; seg < 8; seg++) s += g_kpart[(p * 8 + seg) * 64 + d];
    float kb = s * (1.f / NTOK);
    g_kbar[p * DHEAD + d] = kb;
    __shared__ float sh[64];
    sh[d] = kb;
    __syncthreads();
    if (d == 0) {
        float t = 0.f;
        for (int i = 0; i < 64; i++) t += sh[i];
        g_T[p] = t;
    }
}

// ---------------- a[n] = fq . kbar ; sk[m] = tk[m] - T ----------------------
__global__ void k_ask() {
    int tid = threadIdx.x, w = tid >> 5, lane = tid & 31;
    int t = blockIdx.x * 8 + w;
    int p = t >> 10, n = t & 1023;
    int h = p >> 2, qb = p & 3;
    const float* fq = &g_F[(size_t)(qb * NTOK + n) * DIMV + h * DHEAD];
    const float* kb = &g_kbar[p * DHEAD];
    float s = fq[lane] * kb[lane] + fq[lane + 32] * kb[lane + 32];
    for (int off = 16; off >= 1; off >>= 1) s += __shfl_down_sync(0xffffffffu, s, off);
    if (lane == 0) { g_aq[t] = s; g_sk[t] = g_tk[t] - g_T[p]; }
}

// ---------------- qg/kg two-stage -------------------------------------------
__global__ void k_qgkg1() {
    int h = blockIdx.x, tensor = blockIdx.y, seg = blockIdx.z;
    int tid = threadIdx.x, d = tid & 63, rr = tid >> 6;
    float acc = 0.f;
    for (int r = rr; r < 512; r += 4)
        acc += g_F[(size_t)(tensor * NROWS + seg * 512 + r) * DIMV + h * DHEAD + d];
    __shared__ float red[256];
    red[tid] = acc;
    __syncthreads();
    if (rr == 0)
        g_qgpart[((tensor * 8 + h) * 8 + seg) * 64 + d] = red[d] + red[64 + d] + red[128 + d] + red[192 + d];
}
__global__ void k_qgkg2() {
    int h = blockIdx.x, tensor = blockIdx.y, d = threadIdx.x;
    float s = 0.f;
    for (int seg = 0; seg < 8; seg++) s += g_qgpart[((tensor * 8 + h) * 8 + seg) * 64 + d];
    (tensor == 0 ? g_qg : g_kg)[h * 64 + d] = s * (1.f / NROWS);
}

// ---------------- S = fq @ fk^T (128x128, packed f32x2 FMA) + moments -------
__global__ __launch_bounds__(256) void k_sstats() {
    int p = blockIdx.z, h = p >> 2, qb = p & 3;
    int n0 = blockIdx.y * 128, m0 = blockIdx.x * 128;
    __shared__ float Aq[32][132];
    __shared__ float Bk[32][132];
    __shared__ float rowv[4][128];
    __shared__ float colv[3][128];
    __shared__ float wsum[8];
    int tid = threadIdx.x;
    int tx = tid & 15, ty = tid >> 4;
    int lrow = tid & 127, lkg0 = tid >> 7;
    const float* qsrc = &g_F[(size_t)(qb * NTOK + n0 + lrow) * DIMV + h * DHEAD];
    const float* ksrc = &g_F[(size_t)(NROWS + qb * NTOK + m0 + lrow) * DIMV + h * DHEAD];
    if (tid < 128) {
        int sr = p * NTOK + n0 + tid;
        rowv[0][tid] = g_rncq[sr]; rowv[1][tid] = g_rnsq[sr];
        rowv[2][tid] = g_aq[sr];   rowv[3][tid] = g_mq[sr];
        int sc = p * NTOK + m0 + tid;
        colv[0][tid] = g_rnck[sc]; colv[1][tid] = g_rnsk[sc]; colv[2][tid] = g_sk[sc];
    }
    float4 va[4], vb[4];
    int kc = 0;
#pragma unroll
    for (int it = 0; it < 4; it++) {
        va[it] = *(const float4*)&qsrc[kc + (lkg0 + 2 * it) * 4];
        vb[it] = *(const float4*)&ksrc[kc + (lkg0 + 2 * it) * 4];
    }
    unsigned long long accp[8][4];
#pragma unroll
    for (int i = 0; i < 8; i++)
#pragma unroll
        for (int jp = 0; jp < 4; jp++) accp[i][jp] = 0ull;
    for (int c = 0; c < 2; c++) {
        __syncthreads();
#pragma unroll
        for (int it = 0; it < 4; it++) {
            int kg = (lkg0 + 2 * it) * 4;
            Aq[kg + 0][lrow] = va[it].x; Aq[kg + 1][lrow] = va[it].y;
            Aq[kg + 2][lrow] = va[it].z; Aq[kg + 3][lrow] = va[it].w;
            Bk[kg + 0][lrow] = vb[it].x; Bk[kg + 1][lrow] = vb[it].y;
            Bk[kg + 2][lrow] = vb[it].z; Bk[kg + 3][lrow] = vb[it].w;
        }
        __syncthreads();
        if (c == 0) {
            kc = 32;
#pragma unroll
            for (int it = 0; it < 4; it++) {
                va[it] = *(const float4*)&qsrc[kc + (lkg0 + 2 * it) * 4];
                vb[it] = *(const float4*)&ksrc[kc + (lkg0 + 2 * it) * 4];
            }
        }
#pragma unroll
        for (int kk = 0; kk < 32; kk++) {
            float4 a0 = *(float4*)&Aq[kk][8 * ty];
            float4 a1 = *(float4*)&Aq[kk][8 * ty + 4];
            ulonglong2 b01 = *(ulonglong2*)&Bk[kk][8 * tx];
            ulonglong2 b23 = *(ulonglong2*)&Bk[kk][8 * tx + 4];
            float av[8] = {a0.x, a0.y, a0.z, a0.w, a1.x, a1.y, a1.z, a1.w};
#pragma unroll
            for (int i = 0; i < 8; i++) {
                unsigned long long ap = packdup(av[i]);
                ffma2(accp[i][0], ap, b01.x);
                ffma2(accp[i][1], ap, b01.y);
                ffma2(accp[i][2], ap, b23.x);
                ffma2(accp[i][3], ap, b23.y);
            }
        }
    }
    float acc[8][8];
#pragma unroll
    for (int i = 0; i < 8; i++)
#pragma unroll
        for (int jp = 0; jp < 4; jp++) {
            float2 u = unpack2(accp[i][jp]);
            acc[i][2 * jp] = u.x; acc[i][2 * jp + 1] = u.y;
        }
    float tc = 0.f, tc2 = 0.f, tp = 0.f, tp2 = 0.f, tcp = 0.f;
    size_t sbase = ((size_t)p << 20);
#pragma unroll
    for (int i = 0; i < 8; i++) {
        int row = 8 * ty + i;
        float rq = rowv[0][row], rsq = rowv[1][row];
        float aqv = rowv[2][row], mqv = rowv[3][row];
        float vc = 0.f, vp = 0.f, vm = 0.f;
        float st[8];
#pragma unroll
        for (int j = 0; j < 8; j++) {
            int col = 8 * tx + j;
            float sv = acc[i][j];
            float cosv = fminf(fmaxf(sv * rq * colv[0][col], -0.99f), 0.99f);
            float csim = fminf(fmaxf(sv * rsq * colv[1][col], -0.99f), 0.99f);
            float mar = fminf(fmaxf(0.01f - csim, 0.f), 10.f);
            float pre = (sv - aqv - mqv * colv[2][col]) * INV8;
            tc += cosv; tc2 += cosv * cosv;
            tp += pre;  tp2 += pre * pre; tcp += cosv * pre;
            vc += cosv; vp += pre; vm += mar;
            st[j] = sv;
        }
        size_t so = sbase + (size_t)(n0 + row) * NTOK + m0 + 8 * tx;
        *(float4*)&g_S[so] = make_float4(st[0], st[1], st[2], st[3]);
        *(float4*)&g_S[so + 4] = make_float4(st[4], st[5], st[6], st[7]);
        for (int off = 8; off >= 1; off >>= 1) {
            vc += __shfl_xor_sync(0xffffffffu, vc, off, 16);
            vp += __shfl_xor_sync(0xffffffffu, vp, off, 16);
            vm += __shfl_xor_sync(0xffffffffu, vm, off, 16);
        }
        if (tx == 0) {
            size_t s = (size_t)(p * NTOK + n0 + row) * 8 + blockIdx.x;
            g_rpart[s * 3 + 0] = vc; g_rpart[s * 3 + 1] = vp; g_rpart[s * 3 + 2] = vm;
        }
    }
    float vals[5] = {tc, tc2, tp, tp2, tcp};
    int lane = tid & 31, w = tid >> 5;
    for (int v = 0; v < 5; v++) {
        float x = vals[v];
        for (int off = 16; off >= 1; off >>= 1) x += __shfl_down_sync(0xffffffffu, x, off);
        if (lane == 0) wsum[w] = x;
        __syncthreads();
        if (tid == 0) {
            float s = 0.f;
            for (int i = 0; i < 8; i++) s += wsum[i];
            g_mpart[(size_t)(p * 64 + blockIdx.y * 8 + blockIdx.x) * 5 + v] = (double)s;
        }
        __syncthreads();
    }
}

// ---------------- per-head reductions: rows + moments -----------------------
__global__ void k_rowfinish() {
    int h = blockIdx.x, tid = threadIdx.x;
    double a5 = 0, a6 = 0, a7 = 0, a8 = 0;
    for (int r = tid; r < NROWS; r += 256) {
        int s = h * NROWS + r;
        float rc = 0.f, rp = 0.f, rm = 0.f;
        for (int mb = 0; mb < 8; mb++) {
            size_t idx = ((size_t)s * 8 + mb) * 3;
            rc += g_rpart[idx]; rp += g_rpart[idx + 1]; rm += g_rpart[idx + 2];
        }
        double v = (double)rm * (1.0 / 1024.0);
        a5 += 1024.0 * v; a6 += 1024.0 * v * v;
        a7 += v * (double)rc; a8 += v * (double)rp;
    }
    __shared__ double sh[256];
    double vals[4] = {a5, a6, a7, a8};
    for (int v = 0; v < 4; v++) {
        sh[tid] = vals[v];
        __syncthreads();
        for (int s = 128; s >= 1; s >>= 1) {
            if (tid < s) sh[tid] += sh[tid + s];
            __syncthreads();
        }
        if (tid == 0) g_mom[h * 9 + 5 + v] = sh[0];
        __syncthreads();
    }
    for (int v = 0; v < 5; v++) {
        int qb = tid >> 6, blk = tid & 63;
        sh[tid] = g_mpart[(size_t)((h * 4 + qb) * 64 + blk) * 5 + v];
        __syncthreads();
        for (int s = 128; s >= 1; s >>= 1) {
            if (tid < s) sh[tid] += sh[tid + s];
            __syncthreads();
        }
        if (tid == 0) g_mom[h * 9 + v] = sh[0];
        __syncthreads();
    }
}

__device__ double dev_std(double s, double s2, double N) {
    double v = (s2 - s * s / N) / (N - 1.0);
    return v > 0.0 ? sqrt(v) : 0.0;
}

// ---------------- finalize: MLP weights + global scalars --------------------
__global__ void k_finalize(const float* __restrict__ W1, const float* __restrict__ b1,
                           const float* __restrict__ lng, const float* __restrict__ lnb,
                           const float* __restrict__ W2, const float* __restrict__ b2,
                           const float* __restrict__ W3, const float* __restrict__ b3,
                           const float* __restrict__ wtp) {
    __shared__ float ws[8][3];
    int tid = threadIdx.x;
    if (tid < 8) {
        int h = tid;
        float y[64];
        for (int i = 0; i < 64; i++) {
            float a = b1[i];
            for (int j = 0; j < 64; j++) a += g_qg[h * 64 + j] * W1[j * 64 + i];
            for (int j = 0; j < 64; j++) a += g_kg[h * 64 + j] * W1[(64 + j) * 64 + i];
            y[i] = a;
        }
        float mu = 0.f;
        for (int i = 0; i < 64; i++) mu += y[i];
        mu *= (1.f / 64.f);
        float var = 0.f;
        for (int i = 0; i < 64; i++) { float d = y[i] - mu; var += d * d; }
        float rstd = rsqrtf(var * (1.f / 64.f) + 1e-5f);
        for (int i = 0; i < 64; i++)
            y[i] = fmaxf((y[i] - mu) * rstd * lng[i] + lnb[i], 0.f);
        float hh[32];
        for (int o = 0; o < 32; o++) {
            float a = b2[o];
            for (int i = 0; i < 64; i++) a += y[i] * W2[i * 32 + o];
            hh[o] = fmaxf(a, 0.f);
        }
        float l[3];
        for (int c = 0; c < 3; c++) {
            float a = b3[c];
            for (int o = 0; o < 32; o++) a += hh[o] * W3[o * 3 + c];
            l[c] = a;
        }
        float mx = fmaxf(l[0], fmaxf(l[1], l[2]));
        float e0 = expf(l[0] - mx), e1 = expf(l[1] - mx), e2 = expf(l[2] - mx);
        float sm = e0 + e1 + e2;
        l[0] = e0 / sm; l[1] = e1 / sm; l[2] = e2 / sm;
        float wt = fminf(fmaxf(wtp[0], 0.1f), 20.f);
        l[0] /= wt; l[1] /= wt; l[2] /= wt;
        mx = fmaxf(l[0], fmaxf(l[1], l[2]));
        e0 = expf(l[0] - mx); e1 = expf(l[1] - mx); e2 = expf(l[2] - mx);
        sm = e0 + e1 + e2;
        l[0] = e0 / sm; l[1] = e1 / sm; l[2] = e2 / sm;
        for (int c = 0; c < 3; c++) l[c] = fminf(fmaxf(l[c], 0.05f), 0.8f);
        sm = l[0] + l[1] + l[2];
        ws[h][0] = l[0] / sm; ws[h][1] = l[1] / sm; ws[h][2] = l[2] / sm;
    }
    __syncthreads();
    if (tid == 0) {
        const double N = 33554432.0;
        double Sc = 0, Sc2 = 0, Sp = 0, Sp2 = 0, Sv = 0, Sv2 = 0;
        for (int h = 0; h < 8; h++) {
            Sc += g_mom[h * 9 + 0]; Sc2 += g_mom[h * 9 + 1];
            Sp += g_mom[h * 9 + 2]; Sp2 += g_mom[h * 9 + 3];
            Sv += g_mom[h * 9 + 5]; Sv2 += g_mom[h * 9 + 6];
        }
        double cstd = dev_std(Sc, Sc2, N);
        double pstd = dev_std(Sp, Sp2, N);
        double vstd = dev_std(Sv, Sv2, N);
        double base = 0.001 / 1024.0;
        double reg = (pstd < 1e-6) ? base * 10.0 : base;
        double cn = cstd + 1e-6;
        double covn = reg * pstd + 1e-6;
        double vn = vstd + 1e-6;
        double cscale = (cn < 1e-4) ? 0.1 : 1.0;
        double Sd = 0, Sd2 = 0, al[8], be[8];
        for (int h = 0; h < 8; h++) {
            double a = (double)ws[h][0] * cscale / cn;
            double bb = (double)ws[h][1] * 0.5 / covn;
            double gg = (double)ws[h][2] * 0.5 / vn;
            al[h] = a; be[h] = bb;
            double m0 = g_mom[h * 9 + 0], m1 = g_mom[h * 9 + 1];
            double m2 = g_mom[h * 9 + 2], m3 = g_mom[h * 9 + 3];
            double m4 = g_mom[h * 9 + 4], m5 = g_mom[h * 9 + 5];
            double m6 = g_mom[h * 9 + 6], m7 = g_mom[h * 9 + 7];
            double m8 = g_mom[h * 9 + 8];
            Sd += a * m0 + bb * reg * m2 + gg * m5;
            Sd2 += a * a * m1 + bb * bb * reg * reg * m3 + gg * gg * m6
                 + 2.0 * a * bb * reg * m4 + 2.0 * a * gg * m7 + 2.0 * bb * gg * reg * m8;
        }
        double dvar = (Sd2 - Sd * Sd / N) / (N - 1.0);
        double dstd = dvar > 0.0 ? sqrt(dvar) : 0.0;
        double temp = (dstd < 1e-6) ? 0.1 : 0.3 + dstd;
        temp = fmin(fmax(temp, 0.1), 5.0);
        for (int h = 0; h < 8; h++) {
            g_coef[h] = (float)(al[h] / temp);
            g_coef[8 + h] = (float)(be[h] * reg / temp);
        }
    }
}

// ---------------- online softmax + AV (packed f32x2 AV phase) ---------------
#define VS_PITCH 68
#define PS_PITCH 69
#define SMAV_FLOATS (64 * VS_PITCH + 128 * PS_PITCH + 128 * 3 + 64 * 2)
__global__ __launch_bounds__(256) void k_softmaxAV() {
    extern __shared__ float smp[];
    float (*Vs)[VS_PITCH] = (float(*)[VS_PITCH])smp;
    float (*Ps)[PS_PITCH] = (float(*)[PS_PITCH])(smp + 64 * VS_PITCH);
    float* rq = smp + 64 * VS_PITCH + 128 * PS_PITCH;
    float* aqv = rq + 128;
    float* mqv = aqv + 128;
    float* rk = mqv + 128;
    float* skv = rk + 64;
    int p = blockIdx.y, h = p >> 2, qb = p & 3;
    int n0 = blockIdx.x * 128;
    int tid = threadIdx.x;
    int tx = tid & 15, ty = tid >> 4;
    float cA = g_coef[h], cB = g_coef[8 + h];
    if (tid < 128) {
        int s = p * NTOK + n0 + tid;
        rq[tid] = g_rncq[s]; aqv[tid] = g_aq[s]; mqv[tid] = g_mq[s];
    }
    unsigned long long accp[8][2];
#pragma unroll
    for (int i = 0; i < 8; i++) { accp[i][0] = 0ull; accp[i][1] = 0ull; }
    float rmax[8], den[8] = {};
#pragma unroll
    for (int i = 0; i < 8; i++) rmax[i] = -1e30f;
    size_t sbase = ((size_t)p << 20);
    for (int mt = 0; mt < 16; mt++) {
        int m0 = mt * 64;
        __syncthreads();
#pragma unroll
        for (int it = 0; it < 4; it++) {
            int lin = tid + it * 256;
            int r = lin >> 4, ks = (lin & 15) * 4;
            float4 v4 = *(const float4*)&g_F[(size_t)(2 * NROWS + qb * NTOK + m0 + r) * DIMV + h * DHEAD + ks];
            Vs[r][ks + 0] = v4.x; Vs[r][ks + 1] = v4.y; Vs[r][ks + 2] = v4.z; Vs[r][ks + 3] = v4.w;
        }
        if (tid < 64) {
            int s = p * NTOK + m0 + tid;
            rk[tid] = g_rnck[s]; skv[tid] = g_sk[s];
        }
        __syncthreads();
#pragma unroll
        for (int i = 0; i < 8; i++) {
            int row = 8 * ty + i;
            float4 s4 = *(const float4*)&g_S[sbase + (size_t)(n0 + row) * NTOK + m0 + 4 * tx];
            float rr = rq[row], av = aqv[row], mv = mqv[row];
            float z[4];
#pragma unroll
            for (int j = 0; j < 4; j++) {
                int col = 4 * tx + j;
                float sv = (&s4.x)[j];
                float cosv = fminf(fmaxf(sv * rr * rk[col], -0.99f), 0.99f);
                float pre = (sv - av - mv * skv[col]) * INV8;
                z[j] = cA * cosv + cB * pre;
            }
            float tm = fmaxf(fmaxf(z[0], z[1]), fmaxf(z[2], z[3]));
            for (int off = 8; off >= 1; off >>= 1)
                tm = fmaxf(tm, __shfl_xor_sync(0xffffffffu, tm, off, 16));
            float nm = fmaxf(rmax[i], tm);
            float corr = __expf(rmax[i] - nm);
            float ps = 0.f;
#pragma unroll
            for (int j = 0; j < 4; j++) {
                float pv = __expf(z[j] - nm);
                Ps[row][4 * tx + j] = pv;
                ps += pv;
            }
            for (int off = 8; off >= 1; off >>= 1)
                ps += __shfl_xor_sync(0xffffffffu, ps, off, 16);
            den[i] = den[i] * corr + ps;
            rmax[i] = nm;
            unsigned long long cp = packdup(corr);
            fmul2(accp[i][0], cp);
            fmul2(accp[i][1], cp);
        }
        __syncthreads();
#pragma unroll 4
        for (int m = 0; m < 64; m++) {
            ulonglong2 v2 = *(ulonglong2*)&Vs[m][4 * tx];
#pragma unroll
            for (int i = 0; i < 8; i++) {
                unsigned long long pp = packdup(Ps[8 * ty + i][m]);
                ffma2(accp[i][0], pp, v2.x);
                ffma2(accp[i][1], pp, v2.y);
            }
        }
    }
#pragma unroll
    for (int i = 0; i < 8; i++) {
        float inv = 1.f / den[i];
        int row = n0 + 8 * ty + i;
        float2 u0 = unpack2(accp[i][0]);
        float2 u1 = unpack2(accp[i][1]);
        float4 o;
        o.x = u0.x * inv; o.y = u0.y * inv;
        o.z = u1.x * inv; o.w = u1.y * inv;
        *(float4*)&g_OF[(size_t)(qb * NTOK + row) * DIMV + h * DHEAD + 4 * tx] = o;
    }
}

// ---------------- launch -----------------------------------------------------
extern "C" void kernel_launch(void* const* d_in, const int* in_sizes, int n_in,
                              void* d_out, int out_size) {
    const float* q = (const float*)d_in[0];
    const float* k = (const float*)d_in[1];
    const float* v = (const float*)d_in[2];
    const float* ln_g = (const float*)d_in[3];
    const float* ln_b = (const float*)d_in[4];
    const float* W_in = (const float*)d_in[5];
    const float* wp_W1 = (const float*)d_in[6];
    const float* wp_b1 = (const float*)d_in[7];
    const float* wp_lng = (const float*)d_in[8];
    const float* wp_lnb = (const float*)d_in[9];
    const float* wp_W2 = (const float*)d_in[10];
    const float* wp_b2 = (const float*)d_in[11];
    const float* wp_W3 = (const float*)d_in[12];
    const float* wp_b3 = (const float*)d_in[13];
    const float* wtemp = (const float*)d_in[14];
    const float* W_out = (const float*)d_in[15];
    const float* b_out = (const float*)d_in[16];
    float* out = (float*)d_out;

    float *pXLN, *pF, *pOF;
    cudaGetSymbolAddress((void**)&pXLN, g_XLN);
    cudaGetSymbolAddress((void**)&pF, g_F);
    cudaGetSymbolAddress((void**)&pOF, g_OF);

    cudaFuncSetAttribute(k_softmaxAV, cudaFuncAttributeMaxDynamicSharedMemorySize,
                         SMAV_FLOATS * sizeof(float));

    k_ln<<<NALL, 128>>>(q, k, v, ln_g, ln_b);
    k_mma<<<dim3(DIMV / 128, NALL / 128), 256>>>(pXLN, W_in, nullptr, pF, NALL, DIMV, DIMV);
    k_rowstats<<<8192, 256>>>();
    k_kbar1<<<dim3(NPAIR, 8), 256>>>();
    k_kbar2<<<NPAIR, 64>>>();
    k_ask<<<4096, 256>>>();
    k_qgkg1<<<dim3(NHEAD, 2, 8), 256>>>();
    k_qgkg2<<<dim3(NHEAD, 2), 64>>>();
    k_sstats<<<dim3(8, 8, NPAIR), 256>>>();
    k_rowfinish<<<NHEAD, 256>>>();
    k_finalize<<<1, 32>>>(wp_W1, wp_b1, wp_lng, wp_lnb, wp_W2, wp_b2, wp_W3, wp_b3, wtemp);
    k_softmaxAV<<<dim3(8, NPAIR), 256, SMAV_FLOATS * sizeof(float)>>>();
    k_mma<<<dim3(DIMV / 128, NROWS / 128), 256>>>(pOF, W_out, b_out, out, NROWS, DIMV, DIMV);
}

// round 14
// speedup vs baseline: 1.1218x; 1.0186x over previous
#include <cuda_runtime.h>
#include <math.h>
#include <stdint.h>

#define NTOK 1024
#define DIMV 512
#define NHEAD 8
#define DHEAD 64
#define QBV 4
#define NPAIR 32
#define NROWS 4096
#define NALL 12288
#define NSEG 32768
#define INV8 ((float)(1.0 / (8.0 + 1e-6)))

__device__ float g_XLN[(size_t)NALL * DIMV];
__device__ float g_F[(size_t)NALL * DIMV];
__device__ float g_S[(size_t)NPAIR * NTOK * NTOK];
__device__ float g_OF[(size_t)NROWS * DIMV];
__device__ float g_rncq[NSEG], g_rnsq[NSEG], g_mq[NSEG], g_aq[NSEG];
__device__ float g_rnck[NSEG], g_rnsk[NSEG], g_tk[NSEG], g_sk[NSEG];
__device__ float g_kbar[NPAIR * DHEAD], g_T[NPAIR];
__device__ float g_kpart[NPAIR * 8 * 64];
__device__ float g_qgpart[2 * 8 * 8 * 64];
__device__ float g_qg[NHEAD * DHEAD], g_kg[NHEAD * DHEAD];
__device__ float g_rpart[(size_t)NSEG * 8 * 5];   // per (row, m-block): sumc,sump,summar,maxc,maxp
__device__ double g_mpart[(size_t)NPAIR * 64 * 5];
__device__ double g_mom[NHEAD * 9];
__device__ float g_coef[16];

// ---------------- helpers ---------------------------------------------------
__device__ __forceinline__ uint32_t f2tf32(float x) {
    uint32_t r;
    asm("cvt.rna.tf32.f32 %0, %1;" : "=r"(r) : "f"(x));
    return r;
}
__device__ __forceinline__ void mma_tf32(float* c, const uint32_t* a, uint32_t b0, uint32_t b1) {
    asm volatile(
        "mma.sync.aligned.m16n8k8.row.col.f32.tf32.tf32.f32 "
        "{%0,%1,%2,%3}, {%4,%5,%6,%7}, {%8,%9}, {%0,%1,%2,%3};"
        : "+f"(c[0]), "+f"(c[1]), "+f"(c[2]), "+f"(c[3])
        : "r"(a[0]), "r"(a[1]), "r"(a[2]), "r"(a[3]), "r"(b0), "r"(b1));
}
__device__ __forceinline__ void ffma2(unsigned long long& c, unsigned long long a,
                                      unsigned long long b) {
    asm("fma.rn.f32x2 %0, %1, %2, %0;" : "+l"(c) : "l"(a), "l"(b));
}
__device__ __forceinline__ unsigned long long packdup(float x) {
    unsigned long long r;
    asm("mov.b64 %0, {%1, %1};" : "=l"(r) : "f"(x));
    return r;
}
__device__ __forceinline__ float2 unpack2(unsigned long long v) {
    float2 r;
    asm("mov.b64 {%0, %1}, %2;" : "=f"(r.x), "=f"(r.y) : "l"(v));
    return r;
}

// ---------------- LayerNorm of q,k,v stacked --------------------------------
__global__ void k_ln(const float* __restrict__ q, const float* __restrict__ k,
                     const float* __restrict__ v, const float* __restrict__ g,
                     const float* __restrict__ b) {
    int r = blockIdx.x;
    const float* src = (r < NROWS) ? q + (size_t)r * DIMV
                     : (r < 2 * NROWS) ? k + (size_t)(r - NROWS) * DIMV
                     : v + (size_t)(r - 2 * NROWS) * DIMV;
    int tid = threadIdx.x;  // 128
    float x[4]; float s = 0.f, s2 = 0.f;
#pragma unroll
    for (int j = 0; j < 4; j++) { x[j] = src[tid + j * 128]; s += x[j]; s2 += x[j] * x[j]; }
    __shared__ float shs[4], shs2[4];
    for (int off = 16; off >= 1; off >>= 1) {
        s += __shfl_down_sync(0xffffffffu, s, off);
        s2 += __shfl_down_sync(0xffffffffu, s2, off);
    }
    int lane = tid & 31, w = tid >> 5;
    if (lane == 0) { shs[w] = s; shs2[w] = s2; }
    __syncthreads();
    __shared__ float s_mu, s_rstd;
    if (tid == 0) {
        float S = shs[0] + shs[1] + shs[2] + shs[3];
        float S2 = shs2[0] + shs2[1] + shs2[2] + shs2[3];
        float mu = S / DIMV;
        s_mu = mu; s_rstd = rsqrtf(S2 / DIMV - mu * mu + 1e-5f);
    }
    __syncthreads();
    float mu = s_mu, rstd = s_rstd;
#pragma unroll
    for (int j = 0; j < 4; j++) {
        int c = tid + j * 128;
        g_XLN[(size_t)r * DIMV + c] = (x[j] - mu) * rstd * g[c] + b[c];
    }
}

// ---------------- tf32x2 MMA GEMM: C = A[M,K] @ B[K,N] (+bias) --------------
__global__ __launch_bounds__(256) void k_mma(
        const float* __restrict__ A, const float* __restrict__ B,
        const float* __restrict__ bias, float* __restrict__ C,
        int M, int N, int K) {
    __shared__ float Ah[16][136], Bh[16][136], Bl[16][136];
    int tid = threadIdx.x;
    int lane = tid & 31, wid = tid >> 5;
    int g = lane >> 2, tg = lane & 3;
    int wm = (wid & 3) * 32, wn = (wid >> 2) * 64;
    int m0 = blockIdx.y * 128, n0 = blockIdx.x * 128;
    int arow = tid & 127, akg = tid >> 7;
    int bng = tid & 31, bk0 = tid >> 5;
    const float* Arow = A + (size_t)(m0 + arow) * K;
    float4 va[2], vb[2];
#pragma unroll
    for (int it = 0; it < 2; it++) {
        va[it] = *(const float4*)&Arow[(akg + 2 * it) * 4];
        vb[it] = *(const float4*)&B[(size_t)(bk0 + 8 * it) * N + n0 + bng * 4];
    }
    float acc[2][8][4];
#pragma unroll
    for (int a = 0; a < 2; a++)
#pragma unroll
        for (int b = 0; b < 8; b++)
#pragma unroll
            for (int c = 0; c < 4; c++) acc[a][b][c] = 0.f;
    for (int kc = 0; kc < K; kc += 16) {
        __syncthreads();
#pragma unroll
        for (int it = 0; it < 2; it++) {
            int kka = (akg + 2 * it) * 4;
            float xs[4] = {va[it].x, va[it].y, va[it].z, va[it].w};
#pragma unroll
            for (int c = 0; c < 4; c++)
                Ah[kka + c][arow] = __uint_as_float(f2tf32(xs[c]));
            int kkb = bk0 + 8 * it;
            float ys[4] = {vb[it].x, vb[it].y, vb[it].z, vb[it].w};
            float hb[4], lb[4];
#pragma unroll
            for (int c = 0; c < 4; c++) {
                hb[c] = __uint_as_float(f2tf32(ys[c]));
                lb[c] = __uint_as_float(f2tf32(ys[c] - hb[c]));
            }
            *(float4*)&Bh[kkb][bng * 4] = make_float4(hb[0], hb[1], hb[2], hb[3]);
            *(float4*)&Bl[kkb][bng * 4] = make_float4(lb[0], lb[1], lb[2], lb[3]);
        }
        __syncthreads();
        if (kc + 16 < K) {
            int k0 = kc + 16;
#pragma unroll
            for (int it = 0; it < 2; it++) {
                va[it] = *(const float4*)&Arow[k0 + (akg + 2 * it) * 4];
                vb[it] = *(const float4*)&B[(size_t)(k0 + bk0 + 8 * it) * N + n0 + bng * 4];
            }
        }
#pragma unroll
        for (int ks = 0; ks < 16; ks += 8) {
            uint32_t ah[2][4];
#pragma unroll
            for (int mt = 0; mt < 2; mt++) {
                int mb = wm + mt * 16 + g;
                ah[mt][0] = __float_as_uint(Ah[ks + tg][mb]);
                ah[mt][1] = __float_as_uint(Ah[ks + tg][mb + 8]);
                ah[mt][2] = __float_as_uint(Ah[ks + tg + 4][mb]);
                ah[mt][3] = __float_as_uint(Ah[ks + tg + 4][mb + 8]);
            }
#pragma unroll
            for (int nt = 0; nt < 8; nt++) {
                int nb = wn + nt * 8 + g;
                uint32_t bh0 = __float_as_uint(Bh[ks + tg][nb]);
                uint32_t bh1 = __float_as_uint(Bh[ks + tg + 4][nb]);
                uint32_t bl0 = __float_as_uint(Bl[ks + tg][nb]);
                uint32_t bl1 = __float_as_uint(Bl[ks + tg + 4][nb]);
#pragma unroll
                for (int mt = 0; mt < 2; mt++) {
                    mma_tf32(acc[mt][nt], ah[mt], bh0, bh1);
                    mma_tf32(acc[mt][nt], ah[mt], bl0, bl1);
                }
            }
        }
    }
#pragma unroll
    for (int mt = 0; mt < 2; mt++) {
        int row0 = m0 + wm + mt * 16 + g;
#pragma unroll
        for (int nt = 0; nt < 8; nt++) {
            int col = n0 + wn + nt * 8 + 2 * tg;
            float bx = bias ? bias[col] : 0.f;
            float by = bias ? bias[col + 1] : 0.f;
            *(float2*)&C[(size_t)row0 * N + col] =
                make_float2(acc[mt][nt][0] + bx, acc[mt][nt][1] + by);
            *(float2*)&C[(size_t)(row0 + 8) * N + col] =
                make_float2(acc[mt][nt][2] + bx, acc[mt][nt][3] + by);
        }
    }
}

// ---------------- per (row, head) stats for fq / fk -------------------------
__global__ void k_rowstats() {
    int tid = threadIdx.x;
    int w = tid >> 5, lane = tid & 31;
    int gw = blockIdx.x * 8 + w;
    int tensor = gw >> 15;
    int rem = gw & 32767;
    int row = rem >> 3, h = rem & 7;
    const float* base = &g_F[(size_t)(tensor * NROWS + row) * DIMV + h * DHEAD];
    float v1 = base[lane], v2 = base[lane + 32];
    float s = v1 + v2, sq = v1 * v1 + v2 * v2;
    for (int off = 16; off >= 1; off >>= 1) {
        s += __shfl_down_sync(0xffffffffu, s, off);
        sq += __shfl_down_sync(0xffffffffu, sq, off);
    }
    if (lane == 0) {
        int sidx = h * NROWS + row;
        float nrm = sqrtf(sq);
        if (tensor == 0) {
            g_rncq[sidx] = 1.f / (nrm + 1e-8f);
            g_rnsq[sidx] = 1.f / fmaxf(nrm, 1e-6f);
            g_mq[sidx] = s * (1.f / DHEAD);
        } else {
            g_rnck[sidx] = 1.f / (nrm + 1e-8f);
            g_rnsk[sidx] = 1.f / fmaxf(nrm, 1e-6f);
            g_tk[sidx] = s;
        }
    }
}

// ---------------- kbar two-stage --------------------------------------------
__global__ void k_kbar1() {
    int p = blockIdx.x, seg = blockIdx.y;
    int h = p >> 2, qb = p & 3;
    int tid = threadIdx.x, d = tid & 63, rr = tid >> 6;
    float acc = 0.f;
    int base = qb * NTOK + seg * 128;
    for (int m = rr; m < 128; m += 4)
        acc += g_F[(size_t)(NROWS + base + m) * DIMV + h * DHEAD + d];
    __shared__ float red[256];
    red[tid] = acc;
    __syncthreads();
    if (rr == 0) g_kpart[(p * 8 + seg) * 64 + d] = red[d] + red[64 + d] + red[128 + d] + red[192 + d];
}
__global__ void k_kbar2() {
    int p = blockIdx.x, d = threadIdx.x;
    float s = 0.f;
    for (int seg = 0; seg < 8; seg++) s += g_kpart[(p * 8 + seg) * 64 + d];
    float kb = s * (1.f / NTOK);
    g_kbar[p * DHEAD + d] = kb;
    __shared__ float sh[64];
    sh[d] = kb;
    __syncthreads();
    if (d == 0) {
        float t = 0.f;
        for (int i = 0; i < 64; i++) t += sh[i];
        g_T[p] = t;
    }
}

// ---------------- a[n] = fq . kbar ; sk[m] = tk[m] - T ----------------------
__global__ void k_ask() {
    int tid = threadIdx.x, w = tid >> 5, lane = tid & 31;
    int t = blockIdx.x * 8 + w;
    int p = t >> 10, n = t & 1023;
    int h = p >> 2, qb = p & 3;
    const float* fq = &g_F[(size_t)(qb * NTOK + n) * DIMV + h * DHEAD];
    const float* kb = &g_kbar[p * DHEAD];
    float s = fq[lane] * kb[lane] + fq[lane + 32] * kb[lane + 32];
    for (int off = 16; off >= 1; off >>= 1) s += __shfl_down_sync(0xffffffffu, s, off);
    if (lane == 0) { g_aq[t] = s; g_sk[t] = g_tk[t] - g_T[p]; }
}

// ---------------- qg/kg two-stage -------------------------------------------
__global__ void k_qgkg1() {
    int h = blockIdx.x, tensor = blockIdx.y, seg = blockIdx.z;
    int tid = threadIdx.x, d = tid & 63, rr = tid >> 6;
    float acc = 0.f;
    for (int r = rr; r < 512; r += 4)
        acc += g_F[(size_t)(tensor * NROWS + seg * 512 + r) * DIMV + h * DHEAD + d];
    __shared__ float red[256];
    red[tid] = acc;
    __syncthreads();
    if (rr == 0)
        g_qgpart[((tensor * 8 + h) * 8 + seg) * 64 + d] = red[d] + red[64 + d] + red[128 + d] + red[192 + d];
}
__global__ void k_qgkg2() {
    int h = blockIdx.x, tensor = blockIdx.y, d = threadIdx.x;
    float s = 0.f;
    for (int seg = 0; seg < 8; seg++) s += g_qgpart[((tensor * 8 + h) * 8 + seg) * 64 + d];
    (tensor == 0 ? g_qg : g_kg)[h * 64 + d] = s * (1.f / NROWS);
}

// ---------------- S = fq @ fk^T (128x128, packed f32x2 FMA) + moments -------
__global__ __launch_bounds__(256) void k_sstats() {
    int p = blockIdx.z, h = p >> 2, qb = p & 3;
    int n0 = blockIdx.y * 128, m0 = blockIdx.x * 128;
    __shared__ float Aq[32][132];
    __shared__ float Bk[32][132];
    __shared__ float rowv[4][128];
    __shared__ float colv[3][128];
    __shared__ float wsum[8];
    int tid = threadIdx.x;
    int tx = tid & 15, ty = tid >> 4;
    int lrow = tid & 127, lkg0 = tid >> 7;
    const float* qsrc = &g_F[(size_t)(qb * NTOK + n0 + lrow) * DIMV + h * DHEAD];
    const float* ksrc = &g_F[(size_t)(NROWS + qb * NTOK + m0 + lrow) * DIMV + h * DHEAD];
    if (tid < 128) {
        int sr = p * NTOK + n0 + tid;
        rowv[0][tid] = g_rncq[sr]; rowv[1][tid] = g_rnsq[sr];
        rowv[2][tid] = g_aq[sr];   rowv[3][tid] = g_mq[sr];
        int sc = p * NTOK + m0 + tid;
        colv[0][tid] = g_rnck[sc]; colv[1][tid] = g_rnsk[sc]; colv[2][tid] = g_sk[sc];
    }
    float4 va[4], vb[4];
    int kc = 0;
#pragma unroll
    for (int it = 0; it < 4; it++) {
        va[it] = *(const float4*)&qsrc[kc + (lkg0 + 2 * it) * 4];
        vb[it] = *(const float4*)&ksrc[kc + (lkg0 + 2 * it) * 4];
    }
    unsigned long long accp[8][4];
#pragma unroll
    for (int i = 0; i < 8; i++)
#pragma unroll
        for (int jp = 0; jp < 4; jp++) accp[i][jp] = 0ull;
    for (int c = 0; c < 2; c++) {
        __syncthreads();
#pragma unroll
        for (int it = 0; it < 4; it++) {
            int kg = (lkg0 + 2 * it) * 4;
            Aq[kg + 0][lrow] = va[it].x; Aq[kg + 1][lrow] = va[it].y;
            Aq[kg + 2][lrow] = va[it].z; Aq[kg + 3][lrow] = va[it].w;
            Bk[kg + 0][lrow] = vb[it].x; Bk[kg + 1][lrow] = vb[it].y;
            Bk[kg + 2][lrow] = vb[it].z; Bk[kg + 3][lrow] = vb[it].w;
        }
        __syncthreads();
        if (c == 0) {
            kc = 32;
#pragma unroll
            for (int it = 0; it < 4; it++) {
                va[it] = *(const float4*)&qsrc[kc + (lkg0 + 2 * it) * 4];
                vb[it] = *(const float4*)&ksrc[kc + (lkg0 + 2 * it) * 4];
            }
        }
#pragma unroll
        for (int kk = 0; kk < 32; kk++) {
            float4 a0 = *(float4*)&Aq[kk][8 * ty];
            float4 a1 = *(float4*)&Aq[kk][8 * ty + 4];
            ulonglong2 b01 = *(ulonglong2*)&Bk[kk][8 * tx];
            ulonglong2 b23 = *(ulonglong2*)&Bk[kk][8 * tx + 4];
            float av[8] = {a0.x, a0.y, a0.z, a0.w, a1.x, a1.y, a1.z, a1.w};
#pragma unroll
            for (int i = 0; i < 8; i++) {
                unsigned long long ap = packdup(av[i]);
                ffma2(accp[i][0], ap, b01.x);
                ffma2(accp[i][1], ap, b01.y);
                ffma2(accp[i][2], ap, b23.x);
                ffma2(accp[i][3], ap, b23.y);
            }
        }
    }
    float acc[8][8];
#pragma unroll
    for (int i = 0; i < 8; i++)
#pragma unroll
        for (int jp = 0; jp < 4; jp++) {
            float2 u = unpack2(accp[i][jp]);
            acc[i][2 * jp] = u.x; acc[i][2 * jp + 1] = u.y;
        }
    float tc = 0.f, tc2 = 0.f, tp = 0.f, tp2 = 0.f, tcp = 0.f;
    size_t sbase = ((size_t)p << 20);
#pragma unroll
    for (int i = 0; i < 8; i++) {
        int row = 8 * ty + i;
        float rq = rowv[0][row], rsq = rowv[1][row];
        float aqv = rowv[2][row], mqv = rowv[3][row];
        float vc = 0.f, vp = 0.f, vm = 0.f;
        float mc = -1e30f, mp = -1e30f;
        float st[8];
#pragma unroll
        for (int j = 0; j < 8; j++) {
            int col = 8 * tx + j;
            float sv = acc[i][j];
            float cosv = fminf(fmaxf(sv * rq * colv[0][col], -0.99f), 0.99f);
            float csim = fminf(fmaxf(sv * rsq * colv[1][col], -0.99f), 0.99f);
            float mar = fminf(fmaxf(0.01f - csim, 0.f), 10.f);
            float pre = (sv - aqv - mqv * colv[2][col]) * INV8;
            tc += cosv; tc2 += cosv * cosv;
            tp += pre;  tp2 += pre * pre; tcp += cosv * pre;
            vc += cosv; vp += pre; vm += mar;
            mc = fmaxf(mc, cosv); mp = fmaxf(mp, pre);
            st[j] = sv;
        }
        size_t so = sbase + (size_t)(n0 + row) * NTOK + m0 + 8 * tx;
        *(float4*)&g_S[so] = make_float4(st[0], st[1], st[2], st[3]);
        *(float4*)&g_S[so + 4] = make_float4(st[4], st[5], st[6], st[7]);
        for (int off = 8; off >= 1; off >>= 1) {
            vc += __shfl_xor_sync(0xffffffffu, vc, off, 16);
            vp += __shfl_xor_sync(0xffffffffu, vp, off, 16);
            vm += __shfl_xor_sync(0xffffffffu, vm, off, 16);
            mc = fmaxf(mc, __shfl_xor_sync(0xffffffffu, mc, off, 16));
            mp = fmaxf(mp, __shfl_xor_sync(0xffffffffu, mp, off, 16));
        }
        if (tx == 0) {
            size_t s = (size_t)(p * NTOK + n0 + row) * 8 + blockIdx.x;
            g_rpart[s * 5 + 0] = vc; g_rpart[s * 5 + 1] = vp; g_rpart[s * 5 + 2] = vm;
            g_rpart[s * 5 + 3] = mc; g_rpart[s * 5 + 4] = mp;
        }
    }
    float vals[5] = {tc, tc2, tp, tp2, tcp};
    int lane = tid & 31, w = tid >> 5;
    for (int v = 0; v < 5; v++) {
        float x = vals[v];
        for (int off = 16; off >= 1; off >>= 1) x += __shfl_down_sync(0xffffffffu, x, off);
        if (lane == 0) wsum[w] = x;
        __syncthreads();
        if (tid == 0) {
            float s = 0.f;
            for (int i = 0; i < 8; i++) s += wsum[i];
            g_mpart[(size_t)(p * 64 + blockIdx.y * 8 + blockIdx.x) * 5 + v] = (double)s;
        }
        __syncthreads();
    }
}

// ---------------- per-head reductions: rows + moments -----------------------
__global__ void k_rowfinish() {
    int h = blockIdx.x, tid = threadIdx.x;
    double a5 = 0, a6 = 0, a7 = 0, a8 = 0;
    for (int r = tid; r < NROWS; r += 256) {
        int s = h * NROWS + r;
        float rc = 0.f, rp = 0.f, rm = 0.f;
        for (int mb = 0; mb < 8; mb++) {
            size_t idx = ((size_t)s * 8 + mb) * 5;
            rc += g_rpart[idx]; rp += g_rpart[idx + 1]; rm += g_rpart[idx + 2];
        }
        double v = (double)rm * (1.0 / 1024.0);
        a5 += 1024.0 * v; a6 += 1024.0 * v * v;
        a7 += v * (double)rc; a8 += v * (double)rp;
    }
    __shared__ double sh[256];
    double vals[4] = {a5, a6, a7, a8};
    for (int v = 0; v < 4; v++) {
        sh[tid] = vals[v];
        __syncthreads();
        for (int s = 128; s >= 1; s >>= 1) {
            if (tid < s) sh[tid] += sh[tid + s];
            __syncthreads();
        }
        if (tid == 0) g_mom[h * 9 + 5 + v] = sh[0];
        __syncthreads();
    }
    for (int v = 0; v < 5; v++) {
        int qb = tid >> 6, blk = tid & 63;
        sh[tid] = g_mpart[(size_t)((h * 4 + qb) * 64 + blk) * 5 + v];
        __syncthreads();
        for (int s = 128; s >= 1; s >>= 1) {
            if (tid < s) sh[tid] += sh[tid + s];
            __syncthreads();
        }
        if (tid == 0) g_mom[h * 9 + v] = sh[0];
        __syncthreads();
    }
}

__device__ double dev_std(double s, double s2, double N) {
    double v = (s2 - s * s / N) / (N - 1.0);
    return v > 0.0 ? sqrt(v) : 0.0;
}

// ---------------- finalize: MLP weights + global scalars --------------------
__global__ void k_finalize(const float* __restrict__ W1, const float* __restrict__ b1,
                           const float* __restrict__ lng, const float* __restrict__ lnb,
                           const float* __restrict__ W2, const float* __restrict__ b2,
                           const float* __restrict__ W3, const float* __restrict__ b3,
                           const float* __restrict__ wtp) {
    __shared__ float ws[8][3];
    int tid = threadIdx.x;
    if (tid < 8) {
        int h = tid;
        float y[64];
        for (int i = 0; i < 64; i++) {
            float a = b1[i];
            for (int j = 0; j < 64; j++) a += g_qg[h * 64 + j] * W1[j * 64 + i];
            for (int j = 0; j < 64; j++) a += g_kg[h * 64 + j] * W1[(64 + j) * 64 + i];
            y[i] = a;
        }
        float mu = 0.f;
        for (int i = 0; i < 64; i++) mu += y[i];
        mu *= (1.f / 64.f);
        float var = 0.f;
        for (int i = 0; i < 64; i++) { float d = y[i] - mu; var += d * d; }
        float rstd = rsqrtf(var * (1.f / 64.f) + 1e-5f);
        for (int i = 0; i < 64; i++)
            y[i] = fmaxf((y[i] - mu) * rstd * lng[i] + lnb[i], 0.f);
        float hh[32];
        for (int o = 0; o < 32; o++) {
            float a = b2[o];
            for (int i = 0; i < 64; i++) a += y[i] * W2[i * 32 + o];
            hh[o] = fmaxf(a, 0.f);
        }
        float l[3];
        for (int c = 0; c < 3; c++) {
            float a = b3[c];
            for (int o = 0; o < 32; o++) a += hh[o] * W3[o * 3 + c];
            l[c] = a;
        }
        float mx = fmaxf(l[0], fmaxf(l[1], l[2]));
        float e0 = expf(l[0] - mx), e1 = expf(l[1] - mx), e2 = expf(l[2] - mx);
        float sm = e0 + e1 + e2;
        l[0] = e0 / sm; l[1] = e1 / sm; l[2] = e2 / sm;
        float wt = fminf(fmaxf(wtp[0], 0.1f), 20.f);
        l[0] /= wt; l[1] /= wt; l[2] /= wt;
        mx = fmaxf(l[0], fmaxf(l[1], l[2]));
        e0 = expf(l[0] - mx); e1 = expf(l[1] - mx); e2 = expf(l[2] - mx);
        sm = e0 + e1 + e2;
        l[0] = e0 / sm; l[1] = e1 / sm; l[2] = e2 / sm;
        for (int c = 0; c < 3; c++) l[c] = fminf(fmaxf(l[c], 0.05f), 0.8f);
        sm = l[0] + l[1] + l[2];
        ws[h][0] = l[0] / sm; ws[h][1] = l[1] / sm; ws[h][2] = l[2] / sm;
    }
    __syncthreads();
    if (tid == 0) {
        const double N = 33554432.0;
        double Sc = 0, Sc2 = 0, Sp = 0, Sp2 = 0, Sv = 0, Sv2 = 0;
        for (int h = 0; h < 8; h++) {
            Sc += g_mom[h * 9 + 0]; Sc2 += g_mom[h * 9 + 1];
            Sp += g_mom[h * 9 + 2]; Sp2 += g_mom[h * 9 + 3];
            Sv += g_mom[h * 9 + 5]; Sv2 += g_mom[h * 9 + 6];
        }
        double cstd = dev_std(Sc, Sc2, N);
        double pstd = dev_std(Sp, Sp2, N);
        double vstd = dev_std(Sv, Sv2, N);
        double base = 0.001 / 1024.0;
        double reg = (pstd < 1e-6) ? base * 10.0 : base;
        double cn = cstd + 1e-6;
        double covn = reg * pstd + 1e-6;
        double vn = vstd + 1e-6;
        double cscale = (cn < 1e-4) ? 0.1 : 1.0;
        double Sd = 0, Sd2 = 0, al[8], be[8];
        for (int h = 0; h < 8; h++) {
            double a = (double)ws[h][0] * cscale / cn;
            double bb = (double)ws[h][1] * 0.5 / covn;
            double gg = (double)ws[h][2] * 0.5 / vn;
            al[h] = a; be[h] = bb;
            double m0 = g_mom[h * 9 + 0], m1 = g_mom[h * 9 + 1];
            double m2 = g_mom[h * 9 + 2], m3 = g_mom[h * 9 + 3];
            double m4 = g_mom[h * 9 + 4], m5 = g_mom[h * 9 + 5];
            double m6 = g_mom[h * 9 + 6], m7 = g_mom[h * 9 + 7];
            double m8 = g_mom[h * 9 + 8];
            Sd += a * m0 + bb * reg * m2 + gg * m5;
            Sd2 += a * a * m1 + bb * bb * reg * reg * m3 + gg * gg * m6
                 + 2.0 * a * bb * reg * m4 + 2.0 * a * gg * m7 + 2.0 * bb * gg * reg * m8;
        }
        double dvar = (Sd2 - Sd * Sd / N) / (N - 1.0);
        double dstd = dvar > 0.0 ? sqrt(dvar) : 0.0;
        double temp = (dstd < 1e-6) ? 0.1 : 0.3 + dstd;
        temp = fmin(fmax(temp, 0.1), 5.0);
        for (int h = 0; h < 8; h++) {
            g_coef[h] = (float)(al[h] / temp);
            g_coef[8 + h] = (float)(be[h] * reg / temp);
        }
    }
}

// ------ softmax + AV: bound-based (no online rescale, no per-tile shfl) -----
#define VS_PITCH 68
#define PS_PITCH 69
#define SMAV_FLOATS (64 * VS_PITCH + 128 * PS_PITCH + 128 * 4 + 64 * 2)
__global__ __launch_bounds__(256) void k_softmaxAV() {
    extern __shared__ float smp[];
    float (*Vs)[VS_PITCH] = (float(*)[VS_PITCH])smp;
    float (*Ps)[PS_PITCH] = (float(*)[PS_PITCH])(smp + 64 * VS_PITCH);
    float* rq = smp + 64 * VS_PITCH + 128 * PS_PITCH;
    float* aqv = rq + 128;
    float* mqv = aqv + 128;
    float* zb = mqv + 128;
    float* rk = zb + 128;
    float* skv = rk + 64;
    int p = blockIdx.y, h = p >> 2, qb = p & 3;
    int n0 = blockIdx.x * 128;
    int tid = threadIdx.x;
    int tx = tid & 15, ty = tid >> 4;
    float cA = g_coef[h], cB = g_coef[8 + h];
    if (tid < 128) {
        int s = p * NTOK + n0 + tid;
        rq[tid] = g_rncq[s]; aqv[tid] = g_aq[s]; mqv[tid] = g_mq[s];
        // row softmax bound: cA,cB > 0, so cA*max(cos)+cB*max(pre) >= max(z)
        float zbv = -1e30f;
        for (int mb = 0; mb < 8; mb++) {
            size_t idx = ((size_t)s * 8 + mb) * 5;
            zbv = fmaxf(zbv, cA * g_rpart[idx + 3] + cB * g_rpart[idx + 4]);
        }
        zb[tid] = zbv;
    }
    unsigned long long accp[8][2];
#pragma unroll
    for (int i = 0; i < 8; i++) { accp[i][0] = 0ull; accp[i][1] = 0ull; }
    float den[8] = {};
    size_t sbase = ((size_t)p << 20);
    for (int mt = 0; mt < 16; mt++) {
        int m0 = mt * 64;
        __syncthreads();
#pragma unroll
        for (int it = 0; it < 4; it++) {
            int lin = tid + it * 256;
            int r = lin >> 4, ks = (lin & 15) * 4;
            float4 v4 = *(const float4*)&g_F[(size_t)(2 * NROWS + qb * NTOK + m0 + r) * DIMV + h * DHEAD + ks];
            Vs[r][ks + 0] = v4.x; Vs[r][ks + 1] = v4.y; Vs[r][ks + 2] = v4.z; Vs[r][ks + 3] = v4.w;
        }
        if (tid < 64) {
            int s = p * NTOK + m0 + tid;
            rk[tid] = g_rnck[s]; skv[tid] = g_sk[s];
        }
        __syncthreads();
#pragma unroll
        for (int i = 0; i < 8; i++) {
            int row = 8 * ty + i;
            float4 s4 = *(const float4*)&g_S[sbase + (size_t)(n0 + row) * NTOK + m0 + 4 * tx];
            float rr = rq[row], av = aqv[row], mv = mqv[row], zbr = zb[row];
            float ps = 0.f;
#pragma unroll
            for (int j = 0; j < 4; j++) {
                int col = 4 * tx + j;
                float sv = (&s4.x)[j];
                float cosv = fminf(fmaxf(sv * rr * rk[col], -0.99f), 0.99f);
                float pre = (sv - av - mv * skv[col]) * INV8;
                float pv = __expf(cA * cosv + cB * pre - zbr);
                Ps[row][4 * tx + j] = pv;
                ps += pv;
            }
            den[i] += ps;
        }
        __syncthreads();
#pragma unroll 4
        for (int m = 0; m < 64; m++) {
            ulonglong2 v2 = *(ulonglong2*)&Vs[m][4 * tx];
#pragma unroll
            for (int i = 0; i < 8; i++) {
                unsigned long long pp = packdup(Ps[8 * ty + i][m]);
                ffma2(accp[i][0], pp, v2.x);
                ffma2(accp[i][1], pp, v2.y);
            }
        }
    }
#pragma unroll
    for (int i = 0; i < 8; i++) {
        float d = den[i];
        for (int off = 8; off >= 1; off >>= 1)
            d += __shfl_xor_sync(0xffffffffu, d, off, 16);
        float inv = 1.f / d;
        int row = n0 + 8 * ty + i;
        float2 u0 = unpack2(accp[i][0]);
        float2 u1 = unpack2(accp[i][1]);
        float4 o;
        o.x = u0.x * inv; o.y = u0.y * inv;
        o.z = u1.x * inv; o.w = u1.y * inv;
        *(float4*)&g_OF[(size_t)(qb * NTOK + row) * DIMV + h * DHEAD + 4 * tx] = o;
    }
}

// ---------------- launch -----------------------------------------------------
extern "C" void kernel_launch(void* const* d_in, const int* in_sizes, int n_in,
                              void* d_out, int out_size) {
    const float* q = (const float*)d_in[0];
    const float* k = (const float*)d_in[1];
    const float* v = (const float*)d_in[2];
    const float* ln_g = (const float*)d_in[3];
    const float* ln_b = (const float*)d_in[4];
    const float* W_in = (const float*)d_in[5];
    const float* wp_W1 = (const float*)d_in[6];
    const float* wp_b1 = (const float*)d_in[7];
    const float* wp_lng = (const float*)d_in[8];
    const float* wp_lnb = (const float*)d_in[9];
    const float* wp_W2 = (const float*)d_in[10];
    const float* wp_b2 = (const float*)d_in[11];
    const float* wp_W3 = (const float*)d_in[12];
    const float* wp_b3 = (const float*)d_in[13];
    const float* wtemp = (const float*)d_in[14];
    const float* W_out = (const float*)d_in[15];
    const float* b_out = (const float*)d_in[16];
    float* out = (float*)d_out;

    float *pXLN, *pF, *pOF;
    cudaGetSymbolAddress((void**)&pXLN, g_XLN);
    cudaGetSymbolAddress((void**)&pF, g_F);
    cudaGetSymbolAddress((void**)&pOF, g_OF);

    cudaFuncSetAttribute(k_softmaxAV, cudaFuncAttributeMaxDynamicSharedMemorySize,
                         SMAV_FLOATS * sizeof(float));

    k_ln<<<NALL, 128>>>(q, k, v, ln_g, ln_b);
    k_mma<<<dim3(DIMV / 128, NALL / 128), 256>>>(pXLN, W_in, nullptr, pF, NALL, DIMV, DIMV);
    k_rowstats<<<8192, 256>>>();
    k_kbar1<<<dim3(NPAIR, 8), 256>>>();
    k_kbar2<<<NPAIR, 64>>>();
    k_ask<<<4096, 256>>>();
    k_qgkg1<<<dim3(NHEAD, 2, 8), 256>>>();
    k_qgkg2<<<dim3(NHEAD, 2), 64>>>();
    k_sstats<<<dim3(8, 8, NPAIR), 256>>>();
    k_rowfinish<<<NHEAD, 256>>>();
    k_finalize<<<1, 32>>>(wp_W1, wp_b1, wp_lng, wp_lnb, wp_W2, wp_b2, wp_W3, wp_b3, wtemp);
    k_softmaxAV<<<dim3(8, NPAIR), 256, SMAV_FLOATS * sizeof(float)>>>();
    k_mma<<<dim3(DIMV / 128, NROWS / 128), 256>>>(pOF, W_out, b_out, out, NROWS, DIMV, DIMV);
}

// round 17
// speedup vs baseline: 1.1801x; 1.0519x over previous
#include <cuda_runtime.h>
#include <math.h>
#include <stdint.h>

#define NTOK 1024
#define DIMV 512
#define NHEAD 8
#define DHEAD 64
#define QBV 4
#define NPAIR 32
#define NROWS 4096
#define NALL 12288
#define NSEG 32768
#define INV8 ((float)(1.0 / (8.0 + 1e-6)))

__device__ float g_XLN[(size_t)NALL * DIMV];
__device__ float g_F[(size_t)NALL * DIMV];
__device__ float g_S[(size_t)NPAIR * NTOK * NTOK];
__device__ float g_OF[(size_t)NROWS * DIMV];
__device__ float g_rncq[NSEG], g_rnsq[NSEG], g_mq[NSEG], g_aq[NSEG];
__device__ float g_rnck[NSEG], g_rnsk[NSEG], g_tk[NSEG], g_sk[NSEG];
__device__ float g_kbar[NPAIR * DHEAD], g_T[NPAIR];
__device__ float g_kpart[NPAIR * 8 * 64];
__device__ float g_qgpart[2 * 8 * 8 * 64];
__device__ float g_qg[NHEAD * DHEAD], g_kg[NHEAD * DHEAD];
__device__ float g_rpart[(size_t)NSEG * 16 * 5];  // per (row, halfblock): sumc,sump,summar,maxc,maxp
__device__ double g_mpart[(size_t)NPAIR * 64 * 5];
__device__ double g_mom[NHEAD * 9];
__device__ float g_coef[16];

// ---------------- helpers ---------------------------------------------------
__device__ __forceinline__ uint32_t f2tf32(float x) {
    uint32_t r;
    asm("cvt.rna.tf32.f32 %0, %1;" : "=r"(r) : "f"(x));
    return r;
}
__device__ __forceinline__ void mma_tf32(float* c, const uint32_t* a, uint32_t b0, uint32_t b1) {
    asm volatile(
        "mma.sync.aligned.m16n8k8.row.col.f32.tf32.tf32.f32 "
        "{%0,%1,%2,%3}, {%4,%5,%6,%7}, {%8,%9}, {%0,%1,%2,%3};"
        : "+f"(c[0]), "+f"(c[1]), "+f"(c[2]), "+f"(c[3])
        : "r"(a[0]), "r"(a[1]), "r"(a[2]), "r"(a[3]), "r"(b0), "r"(b1));
}
__device__ __forceinline__ void ffma2(unsigned long long& c, unsigned long long a,
                                      unsigned long long b) {
    asm("fma.rn.f32x2 %0, %1, %2, %0;" : "+l"(c) : "l"(a), "l"(b));
}
__device__ __forceinline__ unsigned long long packdup(float x) {
    unsigned long long r;
    asm("mov.b64 %0, {%1, %1};" : "=l"(r) : "f"(x));
    return r;
}
__device__ __forceinline__ float2 unpack2(unsigned long long v) {
    float2 r;
    asm("mov.b64 {%0, %1}, %2;" : "=f"(r.x), "=f"(r.y) : "l"(v));
    return r;
}

// ---------------- LayerNorm of q,k,v stacked --------------------------------
__global__ void k_ln(const float* __restrict__ q, const float* __restrict__ k,
                     const float* __restrict__ v, const float* __restrict__ g,
                     const float* __restrict__ b) {
    int r = blockIdx.x;
    const float* src = (r < NROWS) ? q + (size_t)r * DIMV
                     : (r < 2 * NROWS) ? k + (size_t)(r - NROWS) * DIMV
                     : v + (size_t)(r - 2 * NROWS) * DIMV;
    int tid = threadIdx.x;  // 128
    float x[4]; float s = 0.f, s2 = 0.f;
#pragma unroll
    for (int j = 0; j < 4; j++) { x[j] = src[tid + j * 128]; s += x[j]; s2 += x[j] * x[j]; }
    __shared__ float shs[4], shs2[4];
    for (int off = 16; off >= 1; off >>= 1) {
        s += __shfl_down_sync(0xffffffffu, s, off);
        s2 += __shfl_down_sync(0xffffffffu, s2, off);
    }
    int lane = tid & 31, w = tid >> 5;
    if (lane == 0) { shs[w] = s; shs2[w] = s2; }
    __syncthreads();
    __shared__ float s_mu, s_rstd;
    if (tid == 0) {
        float S = shs[0] + shs[1] + shs[2] + shs[3];
        float S2 = shs2[0] + shs2[1] + shs2[2] + shs2[3];
        float mu = S / DIMV;
        s_mu = mu; s_rstd = rsqrtf(S2 / DIMV - mu * mu + 1e-5f);
    }
    __syncthreads();
    float mu = s_mu, rstd = s_rstd;
#pragma unroll
    for (int j = 0; j < 4; j++) {
        int c = tid + j * 128;
        g_XLN[(size_t)r * DIMV + c] = (x[j] - mu) * rstd * g[c] + b[c];
    }
}

// ---------------- tf32x2 MMA GEMM: C = A[M,K] @ B[K,N] (+bias) --------------
__global__ __launch_bounds__(256) void k_mma(
        const float* __restrict__ A, const float* __restrict__ B,
        const float* __restrict__ bias, float* __restrict__ C,
        int M, int N, int K) {
    __shared__ float Ah[16][136], Bh[16][136], Bl[16][136];
    int tid = threadIdx.x;
    int lane = tid & 31, wid = tid >> 5;
    int g = lane >> 2, tg = lane & 3;
    int wm = (wid & 3) * 32, wn = (wid >> 2) * 64;
    int m0 = blockIdx.y * 128, n0 = blockIdx.x * 128;
    int arow = tid & 127, akg = tid >> 7;
    int bng = tid & 31, bk0 = tid >> 5;
    const float* Arow = A + (size_t)(m0 + arow) * K;
    float4 va[2], vb[2];
#pragma unroll
    for (int it = 0; it < 2; it++) {
        va[it] = *(const float4*)&Arow[(akg + 2 * it) * 4];
        vb[it] = *(const float4*)&B[(size_t)(bk0 + 8 * it) * N + n0 + bng * 4];
    }
    float acc[2][8][4];
#pragma unroll
    for (int a = 0; a < 2; a++)
#pragma unroll
        for (int b = 0; b < 8; b++)
#pragma unroll
            for (int c = 0; c < 4; c++) acc[a][b][c] = 0.f;
    for (int kc = 0; kc < K; kc += 16) {
        __syncthreads();
#pragma unroll
        for (int it = 0; it < 2; it++) {
            int kka = (akg + 2 * it) * 4;
            float xs[4] = {va[it].x, va[it].y, va[it].z, va[it].w};
#pragma unroll
            for (int c = 0; c < 4; c++)
                Ah[kka + c][arow] = __uint_as_float(f2tf32(xs[c]));
            int kkb = bk0 + 8 * it;
            float ys[4] = {vb[it].x, vb[it].y, vb[it].z, vb[it].w};
            float hb[4], lb[4];
#pragma unroll
            for (int c = 0; c < 4; c++) {
                hb[c] = __uint_as_float(f2tf32(ys[c]));
                lb[c] = __uint_as_float(f2tf32(ys[c] - hb[c]));
            }
            *(float4*)&Bh[kkb][bng * 4] = make_float4(hb[0], hb[1], hb[2], hb[3]);
            *(float4*)&Bl[kkb][bng * 4] = make_float4(lb[0], lb[1], lb[2], lb[3]);
        }
        __syncthreads();
        if (kc + 16 < K) {
            int k0 = kc + 16;
#pragma unroll
            for (int it = 0; it < 2; it++) {
                va[it] = *(const float4*)&Arow[k0 + (akg + 2 * it) * 4];
                vb[it] = *(const float4*)&B[(size_t)(k0 + bk0 + 8 * it) * N + n0 + bng * 4];
            }
        }
#pragma unroll
        for (int ks = 0; ks < 16; ks += 8) {
            uint32_t ah[2][4];
#pragma unroll
            for (int mt = 0; mt < 2; mt++) {
                int mb = wm + mt * 16 + g;
                ah[mt][0] = __float_as_uint(Ah[ks + tg][mb]);
                ah[mt][1] = __float_as_uint(Ah[ks + tg][mb + 8]);
                ah[mt][2] = __float_as_uint(Ah[ks + tg + 4][mb]);
                ah[mt][3] = __float_as_uint(Ah[ks + tg + 4][mb + 8]);
            }
#pragma unroll
            for (int nt = 0; nt < 8; nt++) {
                int nb = wn + nt * 8 + g;
                uint32_t bh0 = __float_as_uint(Bh[ks + tg][nb]);
                uint32_t bh1 = __float_as_uint(Bh[ks + tg + 4][nb]);
                uint32_t bl0 = __float_as_uint(Bl[ks + tg][nb]);
                uint32_t bl1 = __float_as_uint(Bl[ks + tg + 4][nb]);
#pragma unroll
                for (int mt = 0; mt < 2; mt++) {
                    mma_tf32(acc[mt][nt], ah[mt], bh0, bh1);
                    mma_tf32(acc[mt][nt], ah[mt], bl0, bl1);
                }
            }
        }
    }
#pragma unroll
    for (int mt = 0; mt < 2; mt++) {
        int row0 = m0 + wm + mt * 16 + g;
#pragma unroll
        for (int nt = 0; nt < 8; nt++) {
            int col = n0 + wn + nt * 8 + 2 * tg;
            float bx = bias ? bias[col] : 0.f;
            float by = bias ? bias[col + 1] : 0.f;
            *(float2*)&C[(size_t)row0 * N + col] =
                make_float2(acc[mt][nt][0] + bx, acc[mt][nt][1] + by);
            *(float2*)&C[(size_t)(row0 + 8) * N + col] =
                make_float2(acc[mt][nt][2] + bx, acc[mt][nt][3] + by);
        }
    }
}

// ---------------- per (row, head) stats for fq / fk -------------------------
__global__ void k_rowstats() {
    int tid = threadIdx.x;
    int w = tid >> 5, lane = tid & 31;
    int gw = blockIdx.x * 8 + w;
    int tensor = gw >> 15;
    int rem = gw & 32767;
    int row = rem >> 3, h = rem & 7;
    const float* base = &g_F[(size_t)(tensor * NROWS + row) * DIMV + h * DHEAD];
    float v1 = base[lane], v2 = base[lane + 32];
    float s = v1 + v2, sq = v1 * v1 + v2 * v2;
    for (int off = 16; off >= 1; off >>= 1) {
        s += __shfl_down_sync(0xffffffffu, s, off);
        sq += __shfl_down_sync(0xffffffffu, sq, off);
    }
    if (lane == 0) {
        int sidx = h * NROWS + row;
        float nrm = sqrtf(sq);
        if (tensor == 0) {
            g_rncq[sidx] = 1.f / (nrm + 1e-8f);
            g_rnsq[sidx] = 1.f / fmaxf(nrm, 1e-6f);
            g_mq[sidx] = s * (1.f / DHEAD);
        } else {
            g_rnck[sidx] = 1.f / (nrm + 1e-8f);
            g_rnsk[sidx] = 1.f / fmaxf(nrm, 1e-6f);
            g_tk[sidx] = s;
        }
    }
}

// ---------------- kbar two-stage --------------------------------------------
__global__ void k_kbar1() {
    int p = blockIdx.x, seg = blockIdx.y;
    int h = p >> 2, qb = p & 3;
    int tid = threadIdx.x, d = tid & 63, rr = tid >> 6;
    float acc = 0.f;
    int base = qb * NTOK + seg * 128;
    for (int m = rr; m < 128; m += 4)
        acc += g_F[(size_t)(NROWS + base + m) * DIMV + h * DHEAD + d];
    __shared__ float red[256];
    red[tid] = acc;
    __syncthreads();
    if (rr == 0) g_kpart[(p * 8 + seg) * 64 + d] = red[d] + red[64 + d] + red[128 + d] + red[192 + d];
}
__global__ void k_kbar2() {
    int p = blockIdx.x, d = threadIdx.x;
    float s = 0.f;
    for (int seg = 0; seg < 8; seg++) s += g_kpart[(p * 8 + seg) * 64 + d];
    float kb = s * (1.f / NTOK);
    g_kbar[p * DHEAD + d] = kb;
    __shared__ float sh[64];
    sh[d] = kb;
    __syncthreads();
    if (d == 0) {
        float t = 0.f;
        for (int i = 0; i < 64; i++) t += sh[i];
        g_T[p] = t;
    }
}

// ---------------- a[n] = fq . kbar ; sk[m] = tk[m] - T ----------------------
__global__ void k_ask() {
    int tid = threadIdx.x, w = tid >> 5, lane = tid & 31;
    int t = blockIdx.x * 8 + w;
    int p = t >> 10, n = t & 1023;
    int h = p >> 2, qb = p & 3;
    const float* fq = &g_F[(size_t)(qb * NTOK + n) * DIMV + h * DHEAD];
    const float* kb = &g_kbar[p * DHEAD];
    float s = fq[lane] * kb[lane] + fq[lane + 32] * kb[lane + 32];
    for (int off = 16; off >= 1; off >>= 1) s += __shfl_down_sync(0xffffffffu, s, off);
    if (lane == 0) { g_aq[t] = s; g_sk[t] = g_tk[t] - g_T[p]; }
}

// ---------------- qg/kg two-stage -------------------------------------------
__global__ void k_qgkg1() {
    int h = blockIdx.x, tensor = blockIdx.y, seg = blockIdx.z;
    int tid = threadIdx.x, d = tid & 63, rr = tid >> 6;
    float acc = 0.f;
    for (int r = rr; r < 512; r += 4)
        acc += g_F[(size_t)(tensor * NROWS + seg * 512 + r) * DIMV + h * DHEAD + d];
    __shared__ float red[256];
    red[tid] = acc;
    __syncthreads();
    if (rr == 0)
        g_qgpart[((tensor * 8 + h) * 8 + seg) * 64 + d] = red[d] + red[64 + d] + red[128 + d] + red[192 + d];
}
__global__ void k_qgkg2() {
    int h = blockIdx.x, tensor = blockIdx.y, d = threadIdx.x;
    float s = 0.f;
    for (int seg = 0; seg < 8; seg++) s += g_qgpart[((tensor * 8 + h) * 8 + seg) * 64 + d];
    (tensor == 0 ? g_qg : g_kg)[h * 64 + d] = s * (1.f / NROWS);
}

// ------ S = fq @ fk^T via tf32x2 MMA + fused epilogue (moments + maxes) -----
__global__ __launch_bounds__(256) void k_sstats() {
    int p = blockIdx.z, h = p >> 2, qb = p & 3;
    int n0 = blockIdx.y * 128, m0 = blockIdx.x * 128;
    __shared__ float Ah[16][136], Bh[16][136], Bl[16][136];
    __shared__ float rowv[4][128];
    __shared__ float colv[3][128];
    __shared__ float wsum[8];
    int tid = threadIdx.x;
    int lane = tid & 31, wid = tid >> 5;
    int g = lane >> 2, tg = lane & 3;
    int wm = (wid & 3) * 32, wnb = wid >> 2;
    int wn = wnb * 64;
    int lrow = tid & 127, lhalf = tid >> 7;
    const float* qsrc = &g_F[(size_t)(qb * NTOK + n0 + lrow) * DIMV + h * DHEAD];
    const float* ksrc = &g_F[(size_t)(NROWS + qb * NTOK + m0 + lrow) * DIMV + h * DHEAD];
    if (tid < 128) {
        int sr = p * NTOK + n0 + tid;
        rowv[0][tid] = g_rncq[sr]; rowv[1][tid] = g_rnsq[sr];
        rowv[2][tid] = g_aq[sr];   rowv[3][tid] = g_mq[sr];
        int sc = p * NTOK + m0 + tid;
        colv[0][tid] = g_rnck[sc]; colv[1][tid] = g_rnsk[sc]; colv[2][tid] = g_sk[sc];
    }
    float acc[2][8][4];
#pragma unroll
    for (int a = 0; a < 2; a++)
#pragma unroll
        for (int b = 0; b < 8; b++)
#pragma unroll
            for (int c = 0; c < 4; c++) acc[a][b][c] = 0.f;
    for (int kc = 0; kc < 64; kc += 16) {
        float4 va0 = *(const float4*)&qsrc[kc + 8 * lhalf];
        float4 va1 = *(const float4*)&qsrc[kc + 8 * lhalf + 4];
        float4 vb0 = *(const float4*)&ksrc[kc + 8 * lhalf];
        float4 vb1 = *(const float4*)&ksrc[kc + 8 * lhalf + 4];
        __syncthreads();
        float xa[8] = {va0.x, va0.y, va0.z, va0.w, va1.x, va1.y, va1.z, va1.w};
        float xb[8] = {vb0.x, vb0.y, vb0.z, vb0.w, vb1.x, vb1.y, vb1.z, vb1.w};
#pragma unroll
        for (int c = 0; c < 8; c++) {
            int kl = 8 * lhalf + c;
            Ah[kl][lrow] = __uint_as_float(f2tf32(xa[c]));
            float hg = __uint_as_float(f2tf32(xb[c]));
            Bh[kl][lrow] = hg;
            Bl[kl][lrow] = __uint_as_float(f2tf32(xb[c] - hg));
        }
        __syncthreads();
#pragma unroll
        for (int ks = 0; ks < 16; ks += 8) {
            uint32_t ah[2][4];
#pragma unroll
            for (int mt = 0; mt < 2; mt++) {
                int mb = wm + mt * 16 + g;
                ah[mt][0] = __float_as_uint(Ah[ks + tg][mb]);
                ah[mt][1] = __float_as_uint(Ah[ks + tg][mb + 8]);
                ah[mt][2] = __float_as_uint(Ah[ks + tg + 4][mb]);
                ah[mt][3] = __float_as_uint(Ah[ks + tg + 4][mb + 8]);
            }
#pragma unroll
            for (int nt = 0; nt < 8; nt++) {
                int nb = wn + nt * 8 + g;
                uint32_t bh0 = __float_as_uint(Bh[ks + tg][nb]);
                uint32_t bh1 = __float_as_uint(Bh[ks + tg + 4][nb]);
                uint32_t bl0 = __float_as_uint(Bl[ks + tg][nb]);
                uint32_t bl1 = __float_as_uint(Bl[ks + tg + 4][nb]);
#pragma unroll
                for (int mt = 0; mt < 2; mt++) {
                    mma_tf32(acc[mt][nt], ah[mt], bh0, bh1);
                    mma_tf32(acc[mt][nt], ah[mt], bl0, bl1);
                }
            }
        }
    }
    // epilogue: per-element transforms + moments + per-row sums/maxes
    float tc = 0.f, tc2 = 0.f, tp = 0.f, tp2 = 0.f, tcp = 0.f;
    size_t sbase = ((size_t)p << 20);
#pragma unroll
    for (int mt = 0; mt < 2; mt++) {
#pragma unroll
        for (int half = 0; half < 2; half++) {
            int row = wm + mt * 16 + half * 8 + g;
            float rq = rowv[0][row], rsq = rowv[1][row];
            float aqv = rowv[2][row], mqv = rowv[3][row];
            float vc = 0.f, vp = 0.f, vm = 0.f;
            float mc = -1e30f, mp = -1e30f;
#pragma unroll
            for (int nt = 0; nt < 8; nt++) {
                int col0 = wn + nt * 8 + 2 * tg;
                float s0 = acc[mt][nt][half * 2 + 0];
                float s1 = acc[mt][nt][half * 2 + 1];
                float cos0 = fminf(fmaxf(s0 * rq * colv[0][col0], -0.99f), 0.99f);
                float cos1 = fminf(fmaxf(s1 * rq * colv[0][col0 + 1], -0.99f), 0.99f);
                float cs0 = fminf(fmaxf(s0 * rsq * colv[1][col0], -0.99f), 0.99f);
                float cs1 = fminf(fmaxf(s1 * rsq * colv[1][col0 + 1], -0.99f), 0.99f);
                float ma0 = fminf(fmaxf(0.01f - cs0, 0.f), 10.f);
                float ma1 = fminf(fmaxf(0.01f - cs1, 0.f), 10.f);
                float pr0 = (s0 - aqv - mqv * colv[2][col0]) * INV8;
                float pr1 = (s1 - aqv - mqv * colv[2][col0 + 1]) * INV8;
                tc += cos0 + cos1; tc2 += cos0 * cos0 + cos1 * cos1;
                tp += pr0 + pr1;   tp2 += pr0 * pr0 + pr1 * pr1;
                tcp += cos0 * pr0 + cos1 * pr1;
                vc += cos0 + cos1; vp += pr0 + pr1; vm += ma0 + ma1;
                mc = fmaxf(mc, fmaxf(cos0, cos1));
                mp = fmaxf(mp, fmaxf(pr0, pr1));
                *(float2*)&g_S[sbase + (size_t)(n0 + row) * NTOK + m0 + col0] =
                    make_float2(s0, s1);
            }
            // quad reduce (tg = 0..3 share one row)
            vc += __shfl_xor_sync(0xffffffffu, vc, 1, 4);
            vc += __shfl_xor_sync(0xffffffffu, vc, 2, 4);
            vp += __shfl_xor_sync(0xffffffffu, vp, 1, 4);
            vp += __shfl_xor_sync(0xffffffffu, vp, 2, 4);
            vm += __shfl_xor_sync(0xffffffffu, vm, 1, 4);
            vm += __shfl_xor_sync(0xffffffffu, vm, 2, 4);
            mc = fmaxf(mc, __shfl_xor_sync(0xffffffffu, mc, 1, 4));
            mc = fmaxf(mc, __shfl_xor_sync(0xffffffffu, mc, 2, 4));
            mp = fmaxf(mp, __shfl_xor_sync(0xffffffffu, mp, 1, 4));
            mp = fmaxf(mp, __shfl_xor_sync(0xffffffffu, mp, 2, 4));
            if (tg == 0) {
                size_t s = ((size_t)(p * NTOK + n0 + row) * 16 + blockIdx.x * 2 + wnb) * 5;
                g_rpart[s + 0] = vc; g_rpart[s + 1] = vp; g_rpart[s + 2] = vm;
                g_rpart[s + 3] = mc; g_rpart[s + 4] = mp;
            }
        }
    }
    float vals[5] = {tc, tc2, tp, tp2, tcp};
    for (int v = 0; v < 5; v++) {
        float x = vals[v];
        for (int off = 16; off >= 1; off >>= 1) x += __shfl_down_sync(0xffffffffu, x, off);
        if (lane == 0) wsum[wid] = x;
        __syncthreads();
        if (tid == 0) {
            float s = 0.f;
            for (int i = 0; i < 8; i++) s += wsum[i];
            g_mpart[(size_t)(p * 64 + blockIdx.y * 8 + blockIdx.x) * 5 + v] = (double)s;
        }
        __syncthreads();
    }
}

// ---------------- per-head reductions: rows + moments -----------------------
__global__ void k_rowfinish() {
    int h = blockIdx.x, tid = threadIdx.x;
    double a5 = 0, a6 = 0, a7 = 0, a8 = 0;
    for (int r = tid; r < NROWS; r += 256) {
        int s = h * NROWS + r;
        float rc = 0.f, rp = 0.f, rm = 0.f;
        for (int mb = 0; mb < 16; mb++) {
            size_t idx = ((size_t)s * 16 + mb) * 5;
            rc += g_rpart[idx]; rp += g_rpart[idx + 1]; rm += g_rpart[idx + 2];
        }
        double v = (double)rm * (1.0 / 1024.0);
        a5 += 1024.0 * v; a6 += 1024.0 * v * v;
        a7 += v * (double)rc; a8 += v * (double)rp;
    }
    __shared__ double sh[256];
    double vals[4] = {a5, a6, a7, a8};
    for (int v = 0; v < 4; v++) {
        sh[tid] = vals[v];
        __syncthreads();
        for (int s = 128; s >= 1; s >>= 1) {
            if (tid < s) sh[tid] += sh[tid + s];
            __syncthreads();
        }
        if (tid == 0) g_mom[h * 9 + 5 + v] = sh[0];
        __syncthreads();
    }
    for (int v = 0; v < 5; v++) {
        int qb = tid >> 6, blk = tid & 63;
        sh[tid] = g_mpart[(size_t)((h * 4 + qb) * 64 + blk) * 5 + v];
        __syncthreads();
        for (int s = 128; s >= 1; s >>= 1) {
            if (tid < s) sh[tid] += sh[tid + s];
            __syncthreads();
        }
        if (tid == 0) g_mom[h * 9 + v] = sh[0];
        __syncthreads();
    }
}

__device__ double dev_std(double s, double s2, double N) {
    double v = (s2 - s * s / N) / (N - 1.0);
    return v > 0.0 ? sqrt(v) : 0.0;
}

// ---------------- finalize: MLP weights + global scalars --------------------
__global__ void k_finalize(const float* __restrict__ W1, const float* __restrict__ b1,
                           const float* __restrict__ lng, const float* __restrict__ lnb,
                           const float* __restrict__ W2, const float* __restrict__ b2,
                           const float* __restrict__ W3, const float* __restrict__ b3,
                           const float* __restrict__ wtp) {
    __shared__ float ws[8][3];
    int tid = threadIdx.x;
    if (tid < 8) {
        int h = tid;
        float y[64];
        for (int i = 0; i < 64; i++) {
            float a = b1[i];
            for (int j = 0; j < 64; j++) a += g_qg[h * 64 + j] * W1[j * 64 + i];
            for (int j = 0; j < 64; j++) a += g_kg[h * 64 + j] * W1[(64 + j) * 64 + i];
            y[i] = a;
        }
        float mu = 0.f;
        for (int i = 0; i < 64; i++) mu += y[i];
        mu *= (1.f / 64.f);
        float var = 0.f;
        for (int i = 0; i < 64; i++) { float d = y[i] - mu; var += d * d; }
        float rstd = rsqrtf(var * (1.f / 64.f) + 1e-5f);
        for (int i = 0; i < 64; i++)
            y[i] = fmaxf((y[i] - mu) * rstd * lng[i] + lnb[i], 0.f);
        float hh[32];
        for (int o = 0; o < 32; o++) {
            float a = b2[o];
            for (int i = 0; i < 64; i++) a += y[i] * W2[i * 32 + o];
            hh[o] = fmaxf(a, 0.f);
        }
        float l[3];
        for (int c = 0; c < 3; c++) {
            float a = b3[c];
            for (int o = 0; o < 32; o++) a += hh[o] * W3[o * 3 + c];
            l[c] = a;
        }
        float mx = fmaxf(l[0], fmaxf(l[1], l[2]));
        float e0 = expf(l[0] - mx), e1 = expf(l[1] - mx), e2 = expf(l[2] - mx);
        float sm = e0 + e1 + e2;
        l[0] = e0 / sm; l[1] = e1 / sm; l[2] = e2 / sm;
        float wt = fminf(fmaxf(wtp[0], 0.1f), 20.f);
        l[0] /= wt; l[1] /= wt; l[2] /= wt;
        mx = fmaxf(l[0], fmaxf(l[1], l[2]));
        e0 = expf(l[0] - mx); e1 = expf(l[1] - mx); e2 = expf(l[2] - mx);
        sm = e0 + e1 + e2;
        l[0] = e0 / sm; l[1] = e1 / sm; l[2] = e2 / sm;
        for (int c = 0; c < 3; c++) l[c] = fminf(fmaxf(l[c], 0.05f), 0.8f);
        sm = l[0] + l[1] + l[2];
        ws[h][0] = l[0] / sm; ws[h][1] = l[1] / sm; ws[h][2] = l[2] / sm;
    }
    __syncthreads();
    if (tid == 0) {
        const double N = 33554432.0;
        double Sc = 0, Sc2 = 0, Sp = 0, Sp2 = 0, Sv = 0, Sv2 = 0;
        for (int h = 0; h < 8; h++) {
            Sc += g_mom[h * 9 + 0]; Sc2 += g_mom[h * 9 + 1];
            Sp += g_mom[h * 9 + 2]; Sp2 += g_mom[h * 9 + 3];
            Sv += g_mom[h * 9 + 5]; Sv2 += g_mom[h * 9 + 6];
        }
        double cstd = dev_std(Sc, Sc2, N);
        double pstd = dev_std(Sp, Sp2, N);
        double vstd = dev_std(Sv, Sv2, N);
        double base = 0.001 / 1024.0;
        double reg = (pstd < 1e-6) ? base * 10.0 : base;
        double cn = cstd + 1e-6;
        double covn = reg * pstd + 1e-6;
        double vn = vstd + 1e-6;
        double cscale = (cn < 1e-4) ? 0.1 : 1.0;
        double Sd = 0, Sd2 = 0, al[8], be[8];
        for (int h = 0; h < 8; h++) {
            double a = (double)ws[h][0] * cscale / cn;
            double bb = (double)ws[h][1] * 0.5 / covn;
            double gg = (double)ws[h][2] * 0.5 / vn;
            al[h] = a; be[h] = bb;
            double m0 = g_mom[h * 9 + 0], m1 = g_mom[h * 9 + 1];
            double m2 = g_mom[h * 9 + 2], m3 = g_mom[h * 9 + 3];
            double m4 = g_mom[h * 9 + 4], m5 = g_mom[h * 9 + 5];
            double m6 = g_mom[h * 9 + 6], m7 = g_mom[h * 9 + 7];
            double m8 = g_mom[h * 9 + 8];
            Sd += a * m0 + bb * reg * m2 + gg * m5;
            Sd2 += a * a * m1 + bb * bb * reg * reg * m3 + gg * gg * m6
                 + 2.0 * a * bb * reg * m4 + 2.0 * a * gg * m7 + 2.0 * bb * gg * reg * m8;
        }
        double dvar = (Sd2 - Sd * Sd / N) / (N - 1.0);
        double dstd = dvar > 0.0 ? sqrt(dvar) : 0.0;
        double temp = (dstd < 1e-6) ? 0.1 : 0.3 + dstd;
        temp = fmin(fmax(temp, 0.1), 5.0);
        for (int h = 0; h < 8; h++) {
            g_coef[h] = (float)(al[h] / temp);
            g_coef[8 + h] = (float)(be[h] * reg / temp);
        }
    }
}

// ------ softmax + AV: bound-based (no online rescale, no per-tile shfl) -----
#define VS_PITCH 68
#define PS_PITCH 69
#define SMAV_FLOATS (64 * VS_PITCH + 128 * PS_PITCH + 128 * 4 + 64 * 2)
__global__ __launch_bounds__(256) void k_softmaxAV() {
    extern __shared__ float smp[];
    float (*Vs)[VS_PITCH] = (float(*)[VS_PITCH])smp;
    float (*Ps)[PS_PITCH] = (float(*)[PS_PITCH])(smp + 64 * VS_PITCH);
    float* rq = smp + 64 * VS_PITCH + 128 * PS_PITCH;
    float* aqv = rq + 128;
    float* mqv = aqv + 128;
    float* zb = mqv + 128;
    float* rk = zb + 128;
    float* skv = rk + 64;
    int p = blockIdx.y, h = p >> 2, qb = p & 3;
    int n0 = blockIdx.x * 128;
    int tid = threadIdx.x;
    int tx = tid & 15, ty = tid >> 4;
    float cA = g_coef[h], cB = g_coef[8 + h];
    if (tid < 128) {
        int s = p * NTOK + n0 + tid;
        rq[tid] = g_rncq[s]; aqv[tid] = g_aq[s]; mqv[tid] = g_mq[s];
        float zbv = -1e30f;
        for (int mb = 0; mb < 16; mb++) {
            size_t idx = ((size_t)s * 16 + mb) * 5;
            zbv = fmaxf(zbv, cA * g_rpart[idx + 3] + cB * g_rpart[idx + 4]);
        }
        zb[tid] = zbv;
    }
    unsigned long long accp[8][2];
#pragma unroll
    for (int i = 0; i < 8; i++) { accp[i][0] = 0ull; accp[i][1] = 0ull; }
    float den[8] = {};
    size_t sbase = ((size_t)p << 20);
    for (int mt = 0; mt < 16; mt++) {
        int m0 = mt * 64;
        __syncthreads();
#pragma unroll
        for (int it = 0; it < 4; it++) {
            int lin = tid + it * 256;
            int r = lin >> 4, ks = (lin & 15) * 4;
            float4 v4 = *(const float4*)&g_F[(size_t)(2 * NROWS + qb * NTOK + m0 + r) * DIMV + h * DHEAD + ks];
            Vs[r][ks + 0] = v4.x; Vs[r][ks + 1] = v4.y; Vs[r][ks + 2] = v4.z; Vs[r][ks + 3] = v4.w;
        }
        if (tid < 64) {
            int s = p * NTOK + m0 + tid;
            rk[tid] = g_rnck[s]; skv[tid] = g_sk[s];
        }
        __syncthreads();
#pragma unroll
        for (int i = 0; i < 8; i++) {
            int row = 8 * ty + i;
            float4 s4 = *(const float4*)&g_S[sbase + (size_t)(n0 + row) * NTOK + m0 + 4 * tx];
            float rr = rq[row], av = aqv[row], mv = mqv[row], zbr = zb[row];
            float ps = 0.f;
#pragma unroll
            for (int j = 0; j < 4; j++) {
                int col = 4 * tx + j;
                float sv = (&s4.x)[j];
                float cosv = fminf(fmaxf(sv * rr * rk[col], -0.99f), 0.99f);
                float pre = (sv - av - mv * skv[col]) * INV8;
                float pv = __expf(cA * cosv + cB * pre - zbr);
                Ps[row][4 * tx + j] = pv;
                ps += pv;
            }
            den[i] += ps;
        }
        __syncthreads();
#pragma unroll 4
        for (int m = 0; m < 64; m++) {
            ulonglong2 v2 = *(ulonglong2*)&Vs[m][4 * tx];
#pragma unroll
            for (int i = 0; i < 8; i++) {
                unsigned long long pp = packdup(Ps[8 * ty + i][m]);
                ffma2(accp[i][0], pp, v2.x);
                ffma2(accp[i][1], pp, v2.y);
            }
        }
    }
#pragma unroll
    for (int i = 0; i < 8; i++) {
        float d = den[i];
        for (int off = 8; off >= 1; off >>= 1)
            d += __shfl_xor_sync(0xffffffffu, d, off, 16);
        float inv = 1.f / d;
        int row = n0 + 8 * ty + i;
        float2 u0 = unpack2(accp[i][0]);
        float2 u1 = unpack2(accp[i][1]);
        float4 o;
        o.x = u0.x * inv; o.y = u0.y * inv;
        o.z = u1.x * inv; o.w = u1.y * inv;
        *(float4*)&g_OF[(size_t)(qb * NTOK + row) * DIMV + h * DHEAD + 4 * tx] = o;
    }
}

// ---------------- launch -----------------------------------------------------
extern "C" void kernel_launch(void* const* d_in, const int* in_sizes, int n_in,
                              void* d_out, int out_size) {
    const float* q = (const float*)d_in[0];
    const float* k = (const float*)d_in[1];
    const float* v = (const float*)d_in[2];
    const float* ln_g = (const float*)d_in[3];
    const float* ln_b = (const float*)d_in[4];
    const float* W_in = (const float*)d_in[5];
    const float* wp_W1 = (const float*)d_in[6];
    const float* wp_b1 = (const float*)d_in[7];
    const float* wp_lng = (const float*)d_in[8];
    const float* wp_lnb = (const float*)d_in[9];
    const float* wp_W2 = (const float*)d_in[10];
    const float* wp_b2 = (const float*)d_in[11];
    const float* wp_W3 = (const float*)d_in[12];
    const float* wp_b3 = (const float*)d_in[13];
    const float* wtemp = (const float*)d_in[14];
    const float* W_out = (const float*)d_in[15];
    const float* b_out = (const float*)d_in[16];
    float* out = (float*)d_out;

    float *pXLN, *pF, *pOF;
    cudaGetSymbolAddress((void**)&pXLN, g_XLN);
    cudaGetSymbolAddress((void**)&pF, g_F);
    cudaGetSymbolAddress((void**)&pOF, g_OF);

    cudaFuncSetAttribute(k_softmaxAV, cudaFuncAttributeMaxDynamicSharedMemorySize,
                         SMAV_FLOATS * sizeof(float));

    k_ln<<<NALL, 128>>>(q, k, v, ln_g, ln_b);
    k_mma<<<dim3(DIMV / 128, NALL / 128), 256>>>(pXLN, W_in, nullptr, pF, NALL, DIMV, DIMV);
    k_rowstats<<<8192, 256>>>();
    k_kbar1<<<dim3(NPAIR, 8), 256>>>();
    k_kbar2<<<NPAIR, 64>>>();
    k_ask<<<4096, 256>>>();
    k_qgkg1<<<dim3(NHEAD, 2, 8), 256>>>();
    k_qgkg2<<<dim3(NHEAD, 2), 64>>>();
    k_sstats<<<dim3(8, 8, NPAIR), 256>>>();
    k_rowfinish<<<NHEAD, 256>>>();
    k_finalize<<<1, 32>>>(wp_W1, wp_b1, wp_lng, wp_lnb, wp_W2, wp_b2, wp_W3, wp_b3, wtemp);
    k_softmaxAV<<<dim3(8, NPAIR), 256, SMAV_FLOATS * sizeof(float)>>>();
    k_mma<<<dim3(DIMV / 128, NROWS / 128), 256>>>(pOF, W_out, b_out, out, NROWS, DIMV, DIMV);
}